// round 8
// baseline (speedup 1.0000x reference)
#include <cuda_runtime.h>
#include <math.h>
#include <stdint.h>

#define BB 4
#define TT 4096
#define CC 2048
#define HH 128
#define NROW (BB * TT)          // 16384

// Scratch for Q, K, V projections: [B*T, H] each, fp32.
__device__ float g_q[NROW * HH];
__device__ float g_k[NROW * HH];
__device__ float g_v[NROW * HH];

// Fragment-block strides (floats).
// A-fragment block: 32 lanes x 4 words (+pad) -> LDS.128 per fragment.
// B-fragment block: 32 lanes x 2 words (+pad) -> LDS.64 per fragment.
#define KBLK 132
#define NBLK 66

// ---------------------------------------------------------------------------
// tf32 helpers
// ---------------------------------------------------------------------------
__device__ __forceinline__ float ftf32(float x) {
    uint32_t u;
    asm("cvt.rna.tf32.f32 %0, %1;" : "=r"(u) : "f"(x));
    return __uint_as_float(u);
}

__device__ __forceinline__ void mma_tf32(float* d, const float* a, const float* b) {
    asm volatile(
        "mma.sync.aligned.m16n8k8.row.col.f32.tf32.tf32.f32 "
        "{%0,%1,%2,%3}, {%4,%5,%6,%7}, {%8,%9}, {%0,%1,%2,%3};"
        : "+f"(d[0]), "+f"(d[1]), "+f"(d[2]), "+f"(d[3])
        : "r"(__float_as_uint(a[0])), "r"(__float_as_uint(a[1])),
          "r"(__float_as_uint(a[2])), "r"(__float_as_uint(a[3])),
          "r"(__float_as_uint(b[0])), "r"(__float_as_uint(b[1])));
}

// ---------------------------------------------------------------------------
// Kernel 1: fused QKV projection, fragment-major smem + register prefetch.
// Out[row, h] = sum_k idx[row,k] * W[h,k].  BM=128, BN=128, BK=32.
// 8 warps (4x2), warp tile m32 x n64.
// AsF: [kk(4)][ft(8)][KBLK]   BsF: [kk(4)][nt8(16)][NBLK]
// ---------------------------------------------------------------------------
#define QBK 32

__global__ __launch_bounds__(256, 2)
void qkv_kernel(const float* __restrict__ idx,
                const float* __restrict__ Wq,
                const float* __restrict__ Wk,
                const float* __restrict__ Wv)
{
    __shared__ float AsF[4 * 8 * KBLK];      // 4224 floats
    __shared__ float BsF[4 * 16 * NBLK];     // 4224 floats

    const int w = blockIdx.y;
    const float* __restrict__ Wp = (w == 0) ? Wq : (w == 1) ? Wk : Wv;
    float* __restrict__ Out = (w == 0) ? g_q : (w == 1) ? g_k : g_v;

    const int row0 = blockIdx.x * 128;
    const int tid  = threadIdx.x;
    const int warp = tid >> 5, lane = tid & 31;
    const int grp  = lane >> 2, lq = lane & 3;
    const int wm   = warp >> 1;
    const int wn   = warp & 1;

    // per-thread load coords
    int lm[4], lk[4];
#pragma unroll
    for (int i = 0; i < 4; i++) {
        int fi = tid + 256 * i;
        lm[i] = fi >> 3;              // 0..127
        lk[i] = (fi & 7) * 4;         // 0..28
    }
    // precomputed scatter bases
    int abase[4], bbase[4];
#pragma unroll
    for (int i = 0; i < 4; i++) {
        int m = lm[i], c = lk[i];
        int kk = c >> 3;
        abase[i] = ((kk << 3) + (m >> 4)) * KBLK + ((m & 7) << 4)
                 + ((c >> 2) & 1) * 2 + ((m >> 3) & 1);
        bbase[i] = ((kk << 4) + (m >> 3)) * NBLK + ((m & 7) << 3)
                 + ((c >> 2) & 1);
    }

    float4 ra[4], rb[4];
#pragma unroll
    for (int i = 0; i < 4; i++) {
        ra[i] = *(const float4*)(idx + (size_t)(row0 + lm[i]) * CC + lk[i]);
        rb[i] = *(const float4*)(Wp + (size_t)lm[i] * CC + lk[i]);
    }
#pragma unroll
    for (int i = 0; i < 4; i++) {
        AsF[abase[i] + 0]  = ftf32(ra[i].x);
        AsF[abase[i] + 4]  = ftf32(ra[i].y);
        AsF[abase[i] + 8]  = ftf32(ra[i].z);
        AsF[abase[i] + 12] = ftf32(ra[i].w);
        BsF[bbase[i] + 0]  = ftf32(rb[i].x);
        BsF[bbase[i] + 2]  = ftf32(rb[i].y);
        BsF[bbase[i] + 4]  = ftf32(rb[i].z);
        BsF[bbase[i] + 6]  = ftf32(rb[i].w);
    }
    __syncthreads();

    float acc[2][8][4];
#pragma unroll
    for (int mt = 0; mt < 2; mt++)
#pragma unroll
        for (int nt = 0; nt < 8; nt++)
#pragma unroll
            for (int r = 0; r < 4; r++) acc[mt][nt][r] = 0.f;

    for (int k0 = 0; k0 < CC; k0 += QBK) {
        const int kn = k0 + QBK;
        if (kn < CC) {
#pragma unroll
            for (int i = 0; i < 4; i++) {
                ra[i] = *(const float4*)(idx + (size_t)(row0 + lm[i]) * CC + kn + lk[i]);
                rb[i] = *(const float4*)(Wp + (size_t)lm[i] * CC + kn + lk[i]);
            }
        }

#pragma unroll
        for (int kk = 0; kk < 4; kk++) {
            float4 af[2];
#pragma unroll
            for (int mt = 0; mt < 2; mt++)
                af[mt] = *(const float4*)&AsF[((kk << 3) + wm * 2 + mt) * KBLK + (lane << 2)];
            float2 bf[8];
#pragma unroll
            for (int nt = 0; nt < 8; nt++)
                bf[nt] = *(const float2*)&BsF[((kk << 4) + wn * 8 + nt) * NBLK + (lane << 1)];
#pragma unroll
            for (int mt = 0; mt < 2; mt++)
#pragma unroll
                for (int nt = 0; nt < 8; nt++)
                    mma_tf32(acc[mt][nt], (const float*)&af[mt], (const float*)&bf[nt]);
        }
        __syncthreads();

        if (kn < CC) {
#pragma unroll
            for (int i = 0; i < 4; i++) {
                AsF[abase[i] + 0]  = ftf32(ra[i].x);
                AsF[abase[i] + 4]  = ftf32(ra[i].y);
                AsF[abase[i] + 8]  = ftf32(ra[i].z);
                AsF[abase[i] + 12] = ftf32(ra[i].w);
                BsF[bbase[i] + 0]  = ftf32(rb[i].x);
                BsF[bbase[i] + 2]  = ftf32(rb[i].y);
                BsF[bbase[i] + 4]  = ftf32(rb[i].z);
                BsF[bbase[i] + 6]  = ftf32(rb[i].w);
            }
            __syncthreads();
        }
    }

#pragma unroll
    for (int mt = 0; mt < 2; mt++)
#pragma unroll
        for (int nt = 0; nt < 8; nt++) {
            int r = row0 + wm * 32 + mt * 16 + grp;
            int c = wn * 64 + nt * 8 + 2 * lq;
            *(float2*)&Out[(size_t)r * HH + c] =
                make_float2(acc[mt][nt][0], acc[mt][nt][1]);
            *(float2*)&Out[(size_t)(r + 8) * HH + c] =
                make_float2(acc[mt][nt][2], acc[mt][nt][3]);
        }
}

// ---------------------------------------------------------------------------
// Kernel 2: causal attention, flash style, tf32 mma, fragment-major smem.
// S[i,j] = scale * <k_i, q_j>, softmax over j<=i, O[i,:] = sum_j P[i,j] v_j.
// CTA: 64 i-rows resident; j-tiles of width 128. 8 warps 2(m) x 4(n),
// warp tile m32 x n32 both phases.  Pairing (p, 63-p) -> 33 j-tiles/CTA.
// KsF: [kk(16)][ft(4)][KBLK]   QsF/VtF: [kk(16)][nt8(16)][NBLK]
// Ss stays row-major (softmax reduction + PV-A scalar loads).
// ---------------------------------------------------------------------------
#define AM 64
#define AN 128
#define TST 132

#define KSF_FLOATS (16 * 4 * KBLK)       // 8448
#define QVF_FLOATS (16 * 16 * NBLK)      // 16896
#define ATTN_SMEM_FLOATS (KSF_FLOATS + 2 * QVF_FLOATS + AM * TST + 3 * AM)
#define ATTN_SMEM_BYTES  (ATTN_SMEM_FLOATS * 4)

__global__ __launch_bounds__(256, 1)
void attn_kernel(float* __restrict__ out)
{
    extern __shared__ float sm[];
    float* KsF = sm;                       // A fragments of K
    float* QsF = KsF + KSF_FLOATS;         // B fragments of Q
    float* VtF = QsF + QVF_FLOATS;         // B fragments of V^T
    float* Ss  = VtF + QVF_FLOATS;         // [64][132] scores / probs
    float* m_s = Ss + AM * TST;
    float* l_s = m_s + AM;
    float* a_s = l_s + AM;

    const int b    = blockIdx.y;
    const int pair = blockIdx.x;           // 0..31
    const int tid  = threadIdx.x;
    const int warp = tid >> 5, lane = tid & 31;
    const int grp  = lane >> 2, lq = lane & 3;
    const int wm   = warp >> 2;            // 0..1 -> rows wm*32
    const int wn   = warp & 3;             // 0..3 -> cols wn*32

    const float scale = rsqrtf((float)CC);

    for (int phase = 0; phase < 2; phase++) {
        const int ib = (phase == 0) ? pair : 63 - pair;
        const int i0 = ib * AM;
        const int jt = ib >> 1;            // last j-tile index

        // ---- load resident K tile into fragment-major KsF ----
        const float* kbase = g_k + ((size_t)b * TT + i0) * HH;
#pragma unroll
        for (int i = 0; i < 8; i++) {
            int fi = tid + 256 * i;          // 2048 float4
            int r  = fi >> 5;                // 0..63
            int c  = (fi & 31) * 4;          // 0..124
            float4 v = *(const float4*)(kbase + r * HH + c);
            int base = (((c >> 3) << 2) + (r >> 4)) * KBLK + ((r & 7) << 4)
                     + ((c >> 2) & 1) * 2 + ((r >> 3) & 1);
            KsF[base + 0]  = ftf32(v.x);
            KsF[base + 4]  = ftf32(v.y);
            KsF[base + 8]  = ftf32(v.z);
            KsF[base + 12] = ftf32(v.w);
        }
        if (tid < AM) { m_s[tid] = -INFINITY; l_s[tid] = 0.f; }

        float o[2][4][4];
#pragma unroll
        for (int mt = 0; mt < 2; mt++)
#pragma unroll
            for (int nt = 0; nt < 4; nt++)
#pragma unroll
                for (int r = 0; r < 4; r++) o[mt][nt][r] = 0.f;
        __syncthreads();

        for (int jb = 0; jb <= jt; jb++) {
            const int j0 = jb * AN;
            const float* qb = g_q + ((size_t)b * TT + j0) * HH;
            const float* vb = g_v + ((size_t)b * TT + j0) * HH;
#pragma unroll
            for (int i = 0; i < 16; i++) {
                int fi = tid + 256 * i;        // 4096 float4
                int r  = fi >> 5;              // 0..127 (j index)
                int c  = (fi & 31) * 4;        // 0..124 (h index)
                float4 vq = *(const float4*)(qb + r * HH + c);
                int qbase = (((c >> 3) << 4) + (r >> 3)) * NBLK + ((r & 7) << 3)
                          + ((c >> 2) & 1);
                QsF[qbase + 0] = ftf32(vq.x);
                QsF[qbase + 2] = ftf32(vq.y);
                QsF[qbase + 4] = ftf32(vq.z);
                QsF[qbase + 6] = ftf32(vq.w);
                float4 vv = *(const float4*)(vb + r * HH + c);
                // element (h=c+e, j=r):  nt8=(c+e)>>3 const, grp=(c&7)+e
                int vbase = (((r >> 3) << 4) + (c >> 3)) * NBLK + ((c & 7) << 3)
                          + ((r & 3) << 1) + ((r >> 2) & 1);
                VtF[vbase + 0]  = ftf32(vv.x);
                VtF[vbase + 8]  = ftf32(vv.y);
                VtF[vbase + 16] = ftf32(vv.z);
                VtF[vbase + 24] = ftf32(vv.w);
            }
            __syncthreads();

            // ---- S = Ks . Qs^T : warp m32 x n32 ----
            float sfr[2][4][4];
#pragma unroll
            for (int mt = 0; mt < 2; mt++)
#pragma unroll
                for (int nt = 0; nt < 4; nt++)
#pragma unroll
                    for (int r = 0; r < 4; r++) sfr[mt][nt][r] = 0.f;

#pragma unroll
            for (int kk = 0; kk < 16; kk++) {
                float4 af[2];
#pragma unroll
                for (int mt = 0; mt < 2; mt++)
                    af[mt] = *(const float4*)&KsF[((kk << 2) + wm * 2 + mt) * KBLK + (lane << 2)];
                float2 bf[4];
#pragma unroll
                for (int nt = 0; nt < 4; nt++)
                    bf[nt] = *(const float2*)&QsF[((kk << 4) + wn * 4 + nt) * NBLK + (lane << 1)];
#pragma unroll
                for (int mt = 0; mt < 2; mt++)
#pragma unroll
                    for (int nt = 0; nt < 4; nt++)
                        mma_tf32(sfr[mt][nt], (const float*)&af[mt], (const float*)&bf[nt]);
            }

            // ---- scale + causal mask + store to Ss (row-major) ----
            const bool last = (jb == jt);
#pragma unroll
            for (int mt = 0; mt < 2; mt++)
#pragma unroll
                for (int nt = 0; nt < 4; nt++) {
                    int r = wm * 32 + mt * 16 + grp;
                    int c = wn * 32 + nt * 8 + 2 * lq;
                    float v0 = sfr[mt][nt][0] * scale, v1 = sfr[mt][nt][1] * scale;
                    float v2 = sfr[mt][nt][2] * scale, v3 = sfr[mt][nt][3] * scale;
                    if (last) {
                        int ig = i0 + r, jg = j0 + c;
                        if (jg > ig)         v0 = -INFINITY;
                        if (jg + 1 > ig)     v1 = -INFINITY;
                        if (jg > ig + 8)     v2 = -INFINITY;
                        if (jg + 1 > ig + 8) v3 = -INFINITY;
                    }
                    *(float2*)&Ss[r * TST + c]       = make_float2(v0, v1);
                    *(float2*)&Ss[(r + 8) * TST + c] = make_float2(v2, v3);
                }
            __syncthreads();

            // ---- online softmax: 4 threads/row, interleaved cols ----
            {
                const int row = tid >> 2;
                const int q4  = tid & 3;
                float* srow = Ss + row * TST;
                float mx = -INFINITY;
#pragma unroll
                for (int ci = 0; ci < 32; ci++)
                    mx = fmaxf(mx, srow[q4 + 4 * ci]);
                mx = fmaxf(mx, __shfl_xor_sync(0xffffffffu, mx, 1));
                mx = fmaxf(mx, __shfl_xor_sync(0xffffffffu, mx, 2));
                const float m_old = m_s[row];
                const float m_new = fmaxf(m_old, mx);
                float ps = 0.f;
#pragma unroll
                for (int ci = 0; ci < 32; ci++) {
                    float p = __expf(srow[q4 + 4 * ci] - m_new);
                    ps += p;
                    srow[q4 + 4 * ci] = ftf32(p);
                }
                ps += __shfl_xor_sync(0xffffffffu, ps, 1);
                ps += __shfl_xor_sync(0xffffffffu, ps, 2);
                if (q4 == 0) {
                    const float al = __expf(m_old - m_new);
                    a_s[row] = al;
                    l_s[row] = l_s[row] * al + ps;
                    m_s[row] = m_new;
                }
            }
            __syncthreads();

            // ---- O = O*alpha + P @ V : warp m32 x n32 (h cols) ----
            {
                float al[2][2];
#pragma unroll
                for (int mt = 0; mt < 2; mt++) {
                    int m = wm * 32 + mt * 16 + grp;
                    al[mt][0] = a_s[m];
                    al[mt][1] = a_s[m + 8];
                }
#pragma unroll
                for (int mt = 0; mt < 2; mt++)
#pragma unroll
                    for (int nt = 0; nt < 4; nt++) {
                        o[mt][nt][0] *= al[mt][0]; o[mt][nt][1] *= al[mt][0];
                        o[mt][nt][2] *= al[mt][1]; o[mt][nt][3] *= al[mt][1];
                    }
#pragma unroll
                for (int kk = 0; kk < 16; kk++) {
                    const int kb = kk * 8;
                    float a[2][4];
#pragma unroll
                    for (int mt = 0; mt < 2; mt++) {
                        int m = wm * 32 + mt * 16 + grp;
                        a[mt][0] = Ss[m * TST + kb + lq];
                        a[mt][1] = Ss[(m + 8) * TST + kb + lq];
                        a[mt][2] = Ss[m * TST + kb + lq + 4];
                        a[mt][3] = Ss[(m + 8) * TST + kb + lq + 4];
                    }
                    float2 bv[4];
#pragma unroll
                    for (int nt = 0; nt < 4; nt++)
                        bv[nt] = *(const float2*)&VtF[((kk << 4) + wn * 4 + nt) * NBLK + (lane << 1)];
#pragma unroll
                    for (int mt = 0; mt < 2; mt++)
#pragma unroll
                        for (int nt = 0; nt < 4; nt++)
                            mma_tf32(o[mt][nt], a[mt], (const float*)&bv[nt]);
                }
            }
            __syncthreads();
        }

        // ---- epilogue: divide by l, write out ----
        float* obase = out + ((size_t)b * TT + i0) * HH;
#pragma unroll
        for (int mt = 0; mt < 2; mt++) {
            int m = wm * 32 + mt * 16 + grp;
            const float inv0 = 1.f / l_s[m];
            const float inv1 = 1.f / l_s[m + 8];
#pragma unroll
            for (int nt = 0; nt < 4; nt++) {
                int c = wn * 32 + nt * 8 + 2 * lq;
                *(float2*)&obase[(size_t)m * HH + c] =
                    make_float2(o[mt][nt][0] * inv0, o[mt][nt][1] * inv0);
                *(float2*)&obase[(size_t)(m + 8) * HH + c] =
                    make_float2(o[mt][nt][2] * inv1, o[mt][nt][3] * inv1);
            }
        }
        __syncthreads();
    }
}

// ---------------------------------------------------------------------------
extern "C" void kernel_launch(void* const* d_in, const int* in_sizes, int n_in,
                              void* d_out, int out_size)
{
    const float* idx = (const float*)d_in[0];
    const float* Wq  = (const float*)d_in[1];
    const float* Wk  = (const float*)d_in[2];
    const float* Wv  = (const float*)d_in[3];
    float* out = (float*)d_out;

    cudaFuncSetAttribute(attn_kernel,
                         cudaFuncAttributeMaxDynamicSharedMemorySize,
                         ATTN_SMEM_BYTES);

    qkv_kernel<<<dim3(NROW / 128, 3), 256>>>(idx, Wq, Wk, Wv);
    attn_kernel<<<dim3(32, BB), 256, ATTN_SMEM_BYTES>>>(out);
}

// round 9
// speedup vs baseline: 1.1205x; 1.1205x over previous
#include <cuda_runtime.h>
#include <math.h>
#include <stdint.h>

#define BB 4
#define TT 4096
#define CC 2048
#define HH 128
#define NROW (BB * TT)          // 16384

// Scratch for Q, K, V projections: [B*T, H] each, fp32.
__device__ float g_q[NROW * HH];
__device__ float g_k[NROW * HH];
__device__ float g_v[NROW * HH];

// ---------------------------------------------------------------------------
// tf32 helpers
// ---------------------------------------------------------------------------
__device__ __forceinline__ float ftf32(float x) {
    uint32_t u;
    asm("cvt.rna.tf32.f32 %0, %1;" : "=r"(u) : "f"(x));
    return __uint_as_float(u);
}

__device__ __forceinline__ void mma_tf32(float* d, const float* a, const float* b) {
    asm volatile(
        "mma.sync.aligned.m16n8k8.row.col.f32.tf32.tf32.f32 "
        "{%0,%1,%2,%3}, {%4,%5,%6,%7}, {%8,%9}, {%0,%1,%2,%3};"
        : "+f"(d[0]), "+f"(d[1]), "+f"(d[2]), "+f"(d[3])
        : "r"(__float_as_uint(a[0])), "r"(__float_as_uint(a[1])),
          "r"(__float_as_uint(a[2])), "r"(__float_as_uint(a[3])),
          "r"(__float_as_uint(b[0])), "r"(__float_as_uint(b[1])));
}

// ---------------------------------------------------------------------------
// Kernel 1: fused QKV projection with register-prefetch pipeline (R6 version).
// Out[row, h] = sum_k idx[row,k] * W[h,k].  BM=128, BN=128, BK=32.
// 256 threads = 8 warps (4x2), each warp m32 x n64 via m16n8k8 tf32 mma.
// ---------------------------------------------------------------------------
#define QBK 32
#define QKS 36

__global__ __launch_bounds__(256, 2)
void qkv_kernel(const float* __restrict__ idx,
                const float* __restrict__ Wq,
                const float* __restrict__ Wk,
                const float* __restrict__ Wv)
{
    __shared__ float As[128][QKS];
    __shared__ float Bs[128][QKS];

    const int w = blockIdx.y;
    const float* __restrict__ Wp = (w == 0) ? Wq : (w == 1) ? Wk : Wv;
    float* __restrict__ Out = (w == 0) ? g_q : (w == 1) ? g_k : g_v;

    const int row0 = blockIdx.x * 128;
    const int tid  = threadIdx.x;
    const int warp = tid >> 5, lane = tid & 31;
    const int grp  = lane >> 2, lq = lane & 3;
    const int wm   = warp >> 1;
    const int wn   = warp & 1;

    int lm[4], lk[4];
#pragma unroll
    for (int i = 0; i < 4; i++) {
        int fi = tid + 256 * i;
        lm[i] = fi >> 3;
        lk[i] = (fi & 7) * 4;
    }

    float4 ra[4], rb[4];
#pragma unroll
    for (int i = 0; i < 4; i++) {
        ra[i] = *(const float4*)(idx + (size_t)(row0 + lm[i]) * CC + lk[i]);
        rb[i] = *(const float4*)(Wp + (size_t)lm[i] * CC + lk[i]);
    }
#pragma unroll
    for (int i = 0; i < 4; i++) {
        *(float4*)&As[lm[i]][lk[i]] =
            make_float4(ftf32(ra[i].x), ftf32(ra[i].y), ftf32(ra[i].z), ftf32(ra[i].w));
        *(float4*)&Bs[lm[i]][lk[i]] =
            make_float4(ftf32(rb[i].x), ftf32(rb[i].y), ftf32(rb[i].z), ftf32(rb[i].w));
    }
    __syncthreads();

    float acc[2][8][4];
#pragma unroll
    for (int mt = 0; mt < 2; mt++)
#pragma unroll
        for (int nt = 0; nt < 8; nt++)
#pragma unroll
            for (int r = 0; r < 4; r++) acc[mt][nt][r] = 0.f;

    for (int k0 = 0; k0 < CC; k0 += QBK) {
        const int kn = k0 + QBK;
        if (kn < CC) {
#pragma unroll
            for (int i = 0; i < 4; i++) {
                ra[i] = *(const float4*)(idx + (size_t)(row0 + lm[i]) * CC + kn + lk[i]);
                rb[i] = *(const float4*)(Wp + (size_t)lm[i] * CC + kn + lk[i]);
            }
        }

#pragma unroll
        for (int kk = 0; kk < 4; kk++) {
            const int kb = kk * 8;
            float a[2][4], b[8][2];
#pragma unroll
            for (int mt = 0; mt < 2; mt++) {
                int m = wm * 32 + mt * 16 + grp;
                a[mt][0] = As[m][kb + lq];
                a[mt][1] = As[m + 8][kb + lq];
                a[mt][2] = As[m][kb + lq + 4];
                a[mt][3] = As[m + 8][kb + lq + 4];
            }
#pragma unroll
            for (int nt = 0; nt < 8; nt++) {
                int n = wn * 64 + nt * 8 + grp;
                b[nt][0] = Bs[n][kb + lq];
                b[nt][1] = Bs[n][kb + lq + 4];
            }
#pragma unroll
            for (int mt = 0; mt < 2; mt++)
#pragma unroll
                for (int nt = 0; nt < 8; nt++)
                    mma_tf32(acc[mt][nt], a[mt], b[nt]);
        }
        __syncthreads();

        if (kn < CC) {
#pragma unroll
            for (int i = 0; i < 4; i++) {
                *(float4*)&As[lm[i]][lk[i]] =
                    make_float4(ftf32(ra[i].x), ftf32(ra[i].y), ftf32(ra[i].z), ftf32(ra[i].w));
                *(float4*)&Bs[lm[i]][lk[i]] =
                    make_float4(ftf32(rb[i].x), ftf32(rb[i].y), ftf32(rb[i].z), ftf32(rb[i].w));
            }
            __syncthreads();
        }
    }

#pragma unroll
    for (int mt = 0; mt < 2; mt++)
#pragma unroll
        for (int nt = 0; nt < 8; nt++) {
            int r = row0 + wm * 32 + mt * 16 + grp;
            int c = wn * 64 + nt * 8 + 2 * lq;
            *(float2*)&Out[(size_t)r * HH + c] =
                make_float2(acc[mt][nt][0], acc[mt][nt][1]);
            *(float2*)&Out[(size_t)(r + 8) * HH + c] =
                make_float2(acc[mt][nt][2], acc[mt][nt][3]);
        }
}

// ---------------------------------------------------------------------------
// Kernel 2: causal attention, flash style, tf32 mma, 512 threads / 16 warps.
// S[i,j] = scale * <k_i, q_j>, softmax over j<=i, O[i,:] = sum_j P[i,j] v_j.
// CTA: 64 i-rows resident; j-tiles of width 128.
// Warp grid 4(m) x 4(n): each warp m16 x n32 in both phases.
// Persistent pairing (p, 63-p) -> exactly 33 j-tiles per CTA.
// ---------------------------------------------------------------------------
#define AM 64
#define AN 128
#define TST 132     // universal smem stride
#define ATHREADS 512

#define ATTN_SMEM_FLOATS ((AM + AN + HH + AM) * TST + 3 * AM)
#define ATTN_SMEM_BYTES  (ATTN_SMEM_FLOATS * 4)

__global__ __launch_bounds__(ATHREADS, 1)
void attn_kernel(float* __restrict__ out)
{
    extern __shared__ float sm[];
    float* Ks  = sm;                       // [64][132]   K rows (tf32)
    float* Qs  = Ks + AM * TST;            // [128][132]  Q rows (tf32)
    float* Vt  = Qs + AN * TST;            // [128][132]  V transposed [h][j] (tf32)
    float* Ss  = Vt + HH * TST;            // [64][132]   scores / probs
    float* m_s = Ss + AM * TST;            // [64]
    float* l_s = m_s + AM;                 // [64]
    float* a_s = l_s + AM;                 // [64]

    const int b    = blockIdx.y;
    const int pair = blockIdx.x;           // 0..31
    const int tid  = threadIdx.x;
    const int warp = tid >> 5, lane = tid & 31;
    const int grp  = lane >> 2, lq = lane & 3;
    const int wm   = warp >> 2;            // 0..3 -> rows wm*16
    const int wn   = warp & 3;             // 0..3 -> cols wn*32
    const int mrow = wm * 16 + grp;

    const float scale = rsqrtf((float)CC);

    for (int phase = 0; phase < 2; phase++) {
        const int ib = (phase == 0) ? pair : 63 - pair;
        const int i0 = ib * AM;
        const int jt = ib >> 1;            // last j-tile index

        // ---- load resident K tile (tf32-rounded) ----
        const float* kbase = g_k + ((size_t)b * TT + i0) * HH;
#pragma unroll
        for (int i = 0; i < 4; i++) {
            int fi = tid + ATHREADS * i;     // 2048 float4
            int r  = fi >> 5;
            int c  = (fi & 31) * 4;
            float4 v = *(const float4*)(kbase + r * HH + c);
            *(float4*)&Ks[r * TST + c] =
                make_float4(ftf32(v.x), ftf32(v.y), ftf32(v.z), ftf32(v.w));
        }
        if (tid < AM) { m_s[tid] = -INFINITY; l_s[tid] = 0.f; }

        float o[4][4];                       // m16 x n32 (4 n8 tiles)
#pragma unroll
        for (int nt = 0; nt < 4; nt++)
#pragma unroll
            for (int r = 0; r < 4; r++) o[nt][r] = 0.f;
        __syncthreads();

        for (int jb = 0; jb <= jt; jb++) {
            const int j0 = jb * AN;
            const float* qb = g_q + ((size_t)b * TT + j0) * HH;
            const float* vb = g_v + ((size_t)b * TT + j0) * HH;
#pragma unroll
            for (int i = 0; i < 8; i++) {
                int fi = tid + ATHREADS * i;   // 4096 float4
                int r  = fi >> 5;              // 0..127 (j index)
                int c  = (fi & 31) * 4;        // 0..124 (h index)
                float4 vq = *(const float4*)(qb + r * HH + c);
                *(float4*)&Qs[r * TST + c] =
                    make_float4(ftf32(vq.x), ftf32(vq.y), ftf32(vq.z), ftf32(vq.w));
                float4 vv = *(const float4*)(vb + r * HH + c);
                Vt[(c + 0) * TST + r] = ftf32(vv.x);
                Vt[(c + 1) * TST + r] = ftf32(vv.y);
                Vt[(c + 2) * TST + r] = ftf32(vv.z);
                Vt[(c + 3) * TST + r] = ftf32(vv.w);
            }
            __syncthreads();

            // ---- S = Ks . Qs^T : warp m16 (rows wm*16) x n32 (cols wn*32) ----
            float sfr[4][4];
#pragma unroll
            for (int nt = 0; nt < 4; nt++)
#pragma unroll
                for (int r = 0; r < 4; r++) sfr[nt][r] = 0.f;

#pragma unroll
            for (int kk = 0; kk < 16; kk++) {
                const int kb = kk * 8;
                float a[4], bq[4][2];
                a[0] = Ks[mrow * TST + kb + lq];
                a[1] = Ks[(mrow + 8) * TST + kb + lq];
                a[2] = Ks[mrow * TST + kb + lq + 4];
                a[3] = Ks[(mrow + 8) * TST + kb + lq + 4];
#pragma unroll
                for (int nt = 0; nt < 4; nt++) {
                    int n = wn * 32 + nt * 8 + grp;
                    bq[nt][0] = Qs[n * TST + kb + lq];
                    bq[nt][1] = Qs[n * TST + kb + lq + 4];
                }
#pragma unroll
                for (int nt = 0; nt < 4; nt++)
                    mma_tf32(sfr[nt], a, bq[nt]);
            }

            // ---- scale + causal mask + store to Ss ----
            const bool last = (jb == jt);
#pragma unroll
            for (int nt = 0; nt < 4; nt++) {
                int r = wm * 16 + grp;
                int c = wn * 32 + nt * 8 + 2 * lq;
                float v0 = sfr[nt][0] * scale, v1 = sfr[nt][1] * scale;
                float v2 = sfr[nt][2] * scale, v3 = sfr[nt][3] * scale;
                if (last) {
                    int ig = i0 + r, jg = j0 + c;
                    if (jg > ig)         v0 = -INFINITY;
                    if (jg + 1 > ig)     v1 = -INFINITY;
                    if (jg > ig + 8)     v2 = -INFINITY;
                    if (jg + 1 > ig + 8) v3 = -INFINITY;
                }
                *(float2*)&Ss[r * TST + c]       = make_float2(v0, v1);
                *(float2*)&Ss[(r + 8) * TST + c] = make_float2(v2, v3);
            }
            __syncthreads();

            // ---- online softmax: 8 threads/row, interleaved cols ----
            {
                const int row = tid >> 3;      // 0..63
                const int q8  = tid & 7;
                float* srow = Ss + row * TST;
                float mx = -INFINITY;
#pragma unroll
                for (int ci = 0; ci < 16; ci++)
                    mx = fmaxf(mx, srow[q8 + 8 * ci]);
                mx = fmaxf(mx, __shfl_xor_sync(0xffffffffu, mx, 1));
                mx = fmaxf(mx, __shfl_xor_sync(0xffffffffu, mx, 2));
                mx = fmaxf(mx, __shfl_xor_sync(0xffffffffu, mx, 4));
                const float m_old = m_s[row];
                const float m_new = fmaxf(m_old, mx);
                float ps = 0.f;
#pragma unroll
                for (int ci = 0; ci < 16; ci++) {
                    float p = __expf(srow[q8 + 8 * ci] - m_new);
                    ps += p;
                    srow[q8 + 8 * ci] = ftf32(p);
                }
                ps += __shfl_xor_sync(0xffffffffu, ps, 1);
                ps += __shfl_xor_sync(0xffffffffu, ps, 2);
                ps += __shfl_xor_sync(0xffffffffu, ps, 4);
                if (q8 == 0) {
                    const float al = __expf(m_old - m_new);
                    a_s[row] = al;
                    l_s[row] = l_s[row] * al + ps;
                    m_s[row] = m_new;
                }
            }
            __syncthreads();

            // ---- O = O*alpha + P @ V : warp m16 x n32 (h cols wn*32) ----
            {
                const float al0 = a_s[mrow];
                const float al1 = a_s[mrow + 8];
#pragma unroll
                for (int nt = 0; nt < 4; nt++) {
                    o[nt][0] *= al0; o[nt][1] *= al0;
                    o[nt][2] *= al1; o[nt][3] *= al1;
                }
#pragma unroll
                for (int kk = 0; kk < 16; kk++) {
                    const int kb = kk * 8;
                    float a[4], bv[4][2];
                    a[0] = Ss[mrow * TST + kb + lq];
                    a[1] = Ss[(mrow + 8) * TST + kb + lq];
                    a[2] = Ss[mrow * TST + kb + lq + 4];
                    a[3] = Ss[(mrow + 8) * TST + kb + lq + 4];
#pragma unroll
                    for (int nt = 0; nt < 4; nt++) {
                        int n = wn * 32 + nt * 8 + grp;   // h index
                        bv[nt][0] = Vt[n * TST + kb + lq];
                        bv[nt][1] = Vt[n * TST + kb + lq + 4];
                    }
#pragma unroll
                    for (int nt = 0; nt < 4; nt++)
                        mma_tf32(o[nt], a, bv[nt]);
                }
            }
            __syncthreads();   // protect Qs/Vt/Ss before next tile load
        }

        // ---- epilogue: divide by l, write out ----
        const float inv0 = 1.f / l_s[mrow];
        const float inv1 = 1.f / l_s[mrow + 8];
        float* obase = out + ((size_t)b * TT + i0) * HH;
#pragma unroll
        for (int nt = 0; nt < 4; nt++) {
            int c = wn * 32 + nt * 8 + 2 * lq;
            *(float2*)&obase[(size_t)mrow * HH + c] =
                make_float2(o[nt][0] * inv0, o[nt][1] * inv0);
            *(float2*)&obase[(size_t)(mrow + 8) * HH + c] =
                make_float2(o[nt][2] * inv1, o[nt][3] * inv1);
        }
        __syncthreads();   // done with smem before next phase reloads
    }
}

// ---------------------------------------------------------------------------
extern "C" void kernel_launch(void* const* d_in, const int* in_sizes, int n_in,
                              void* d_out, int out_size)
{
    const float* idx = (const float*)d_in[0];
    const float* Wq  = (const float*)d_in[1];
    const float* Wk  = (const float*)d_in[2];
    const float* Wv  = (const float*)d_in[3];
    float* out = (float*)d_out;

    cudaFuncSetAttribute(attn_kernel,
                         cudaFuncAttributeMaxDynamicSharedMemorySize,
                         ATTN_SMEM_BYTES);

    qkv_kernel<<<dim3(NROW / 128, 3), 256>>>(idx, Wq, Wk, Wv);
    attn_kernel<<<dim3(32, BB), ATHREADS, ATTN_SMEM_BYTES>>>(out);
}

// round 12
// speedup vs baseline: 1.5358x; 1.3706x over previous
#include <cuda_runtime.h>
#include <cuda_bf16.h>
#include <math.h>
#include <stdint.h>

#define BB 4
#define TT 4096
#define CC 2048
#define HH 128
#define NROW (BB * TT)          // 16384

// Scratch for Q, K, V projections: [B*T, H] each, fp32.
__device__ float g_q[NROW * HH];
__device__ float g_k[NROW * HH];
__device__ float g_v[NROW * HH];

// ---------------------------------------------------------------------------
// helpers
// ---------------------------------------------------------------------------
__device__ __forceinline__ float ftf32(float x) {
    uint32_t u;
    asm("cvt.rna.tf32.f32 %0, %1;" : "=r"(u) : "f"(x));
    return __uint_as_float(u);
}

__device__ __forceinline__ uint32_t bf16pair(float lo, float hi) {
    uint32_t r;
    asm("cvt.rn.bf16x2.f32 %0, %1, %2;" : "=r"(r) : "f"(hi), "f"(lo));
    return r;
}

__device__ __forceinline__ void mma_tf32(float* d, const float* a, const float* b) {
    asm volatile(
        "mma.sync.aligned.m16n8k8.row.col.f32.tf32.tf32.f32 "
        "{%0,%1,%2,%3}, {%4,%5,%6,%7}, {%8,%9}, {%0,%1,%2,%3};"
        : "+f"(d[0]), "+f"(d[1]), "+f"(d[2]), "+f"(d[3])
        : "r"(__float_as_uint(a[0])), "r"(__float_as_uint(a[1])),
          "r"(__float_as_uint(a[2])), "r"(__float_as_uint(a[3])),
          "r"(__float_as_uint(b[0])), "r"(__float_as_uint(b[1])));
}

__device__ __forceinline__ void mma_bf16(float* d, const uint32_t* a, const uint32_t* b) {
    asm volatile(
        "mma.sync.aligned.m16n8k16.row.col.f32.bf16.bf16.f32 "
        "{%0,%1,%2,%3}, {%4,%5,%6,%7}, {%8,%9}, {%0,%1,%2,%3};"
        : "+f"(d[0]), "+f"(d[1]), "+f"(d[2]), "+f"(d[3])
        : "r"(a[0]), "r"(a[1]), "r"(a[2]), "r"(a[3]),
          "r"(b[0]), "r"(b[1]));
}

// ---------------------------------------------------------------------------
// Kernel 1: fused QKV projection (R6 version: register prefetch, tf32 mma).
// ---------------------------------------------------------------------------
#define QBK 32
#define QKS 36

__global__ __launch_bounds__(256, 2)
void qkv_kernel(const float* __restrict__ idx,
                const float* __restrict__ Wq,
                const float* __restrict__ Wk,
                const float* __restrict__ Wv)
{
    __shared__ float As[128][QKS];
    __shared__ float Bs[128][QKS];

    const int w = blockIdx.y;
    const float* __restrict__ Wp = (w == 0) ? Wq : (w == 1) ? Wk : Wv;
    float* __restrict__ Out = (w == 0) ? g_q : (w == 1) ? g_k : g_v;

    const int row0 = blockIdx.x * 128;
    const int tid  = threadIdx.x;
    const int warp = tid >> 5, lane = tid & 31;
    const int grp  = lane >> 2, lq = lane & 3;
    const int wm   = warp >> 1;
    const int wn   = warp & 1;

    int lm[4], lk[4];
#pragma unroll
    for (int i = 0; i < 4; i++) {
        int fi = tid + 256 * i;
        lm[i] = fi >> 3;
        lk[i] = (fi & 7) * 4;
    }

    float4 ra[4], rb[4];
#pragma unroll
    for (int i = 0; i < 4; i++) {
        ra[i] = *(const float4*)(idx + (size_t)(row0 + lm[i]) * CC + lk[i]);
        rb[i] = *(const float4*)(Wp + (size_t)lm[i] * CC + lk[i]);
    }
#pragma unroll
    for (int i = 0; i < 4; i++) {
        *(float4*)&As[lm[i]][lk[i]] =
            make_float4(ftf32(ra[i].x), ftf32(ra[i].y), ftf32(ra[i].z), ftf32(ra[i].w));
        *(float4*)&Bs[lm[i]][lk[i]] =
            make_float4(ftf32(rb[i].x), ftf32(rb[i].y), ftf32(rb[i].z), ftf32(rb[i].w));
    }
    __syncthreads();

    float acc[2][8][4];
#pragma unroll
    for (int mt = 0; mt < 2; mt++)
#pragma unroll
        for (int nt = 0; nt < 8; nt++)
#pragma unroll
            for (int r = 0; r < 4; r++) acc[mt][nt][r] = 0.f;

    for (int k0 = 0; k0 < CC; k0 += QBK) {
        const int kn = k0 + QBK;
        if (kn < CC) {
#pragma unroll
            for (int i = 0; i < 4; i++) {
                ra[i] = *(const float4*)(idx + (size_t)(row0 + lm[i]) * CC + kn + lk[i]);
                rb[i] = *(const float4*)(Wp + (size_t)lm[i] * CC + kn + lk[i]);
            }
        }

#pragma unroll
        for (int kk = 0; kk < 4; kk++) {
            const int kb = kk * 8;
            float a[2][4], b[8][2];
#pragma unroll
            for (int mt = 0; mt < 2; mt++) {
                int m = wm * 32 + mt * 16 + grp;
                a[mt][0] = As[m][kb + lq];
                a[mt][1] = As[m + 8][kb + lq];
                a[mt][2] = As[m][kb + lq + 4];
                a[mt][3] = As[m + 8][kb + lq + 4];
            }
#pragma unroll
            for (int nt = 0; nt < 8; nt++) {
                int n = wn * 64 + nt * 8 + grp;
                b[nt][0] = Bs[n][kb + lq];
                b[nt][1] = Bs[n][kb + lq + 4];
            }
#pragma unroll
            for (int mt = 0; mt < 2; mt++)
#pragma unroll
                for (int nt = 0; nt < 8; nt++)
                    mma_tf32(acc[mt][nt], a[mt], b[nt]);
        }
        __syncthreads();

        if (kn < CC) {
#pragma unroll
            for (int i = 0; i < 4; i++) {
                *(float4*)&As[lm[i]][lk[i]] =
                    make_float4(ftf32(ra[i].x), ftf32(ra[i].y), ftf32(ra[i].z), ftf32(ra[i].w));
                *(float4*)&Bs[lm[i]][lk[i]] =
                    make_float4(ftf32(rb[i].x), ftf32(rb[i].y), ftf32(rb[i].z), ftf32(rb[i].w));
            }
            __syncthreads();
        }
    }

#pragma unroll
    for (int mt = 0; mt < 2; mt++)
#pragma unroll
        for (int nt = 0; nt < 8; nt++) {
            int r = row0 + wm * 32 + mt * 16 + grp;
            int c = wn * 64 + nt * 8 + 2 * lq;
            *(float2*)&Out[(size_t)r * HH + c] =
                make_float2(acc[mt][nt][0], acc[mt][nt][1]);
            *(float2*)&Out[(size_t)(r + 8) * HH + c] =
                make_float2(acc[mt][nt][2], acc[mt][nt][3]);
        }
}

// ---------------------------------------------------------------------------
// Kernel 2: causal attention, register-resident P, no-max softmax.
// S[i,j] = <k_i, q_j> (bf16 mma);  P = exp(scale*S) masked (reg only);
// O[i,:] += P @ V (tf32 mma, A built from P regs via quad shuffles).
// CTA: 64 i-rows; j-tiles of 128. 8 warps: wm in {0,1} (rows wm*32, m32),
// wn in {0..3} (j-slice wn*32).  Each warp: S m32 x n32 (its j-slice),
// PV k=32 (same slice) x n=128 (all h), O in regs (128/thread),
// cross-warp O/l reduction once per phase.  Pairing (p, 63-p).
// ---------------------------------------------------------------------------
#define AM 64
#define AN 128
#define KQST 136     // u16 row stride for Kb/Qb (conflict-free fragment LDS)
#define VST2 136     // float row stride for Vs
#define ORST 132     // float row stride for Ored

// smem byte offsets
#define SM_KB   0                         // u16  [64][136]  = 17408
#define SM_QB   17408                     // u16  [128][136] = 34816
#define SM_VS   52224                     // f32  [128][136] = 69632
#define SM_OR   121856                    // f32  [64][132]  = 33792
#define SM_L4   155648                    // f32  [64][4]    = 1024
#define SM_LI   156672                    // f32  [64]       = 256
#define ATTN_SMEM_BYTES 156928

__global__ __launch_bounds__(256, 1)
void attn_kernel(float* __restrict__ out)
{
    extern __shared__ char smc[];
    uint16_t* Kb = (uint16_t*)(smc + SM_KB);   // bf16 bits
    uint16_t* Qb = (uint16_t*)(smc + SM_QB);   // bf16 bits
    float* Vs   = (float*)(smc + SM_VS);
    float* Ored = (float*)(smc + SM_OR);
    float* l4   = (float*)(smc + SM_L4);
    float* linv = (float*)(smc + SM_LI);

    const int b    = blockIdx.y;
    const int pair = blockIdx.x;           // 0..31
    const int tid  = threadIdx.x;
    const int warp = tid >> 5, lane = tid & 31;
    const int grp  = lane >> 2, lq = lane & 3;
    const int wm   = warp >> 2;            // 0..1 -> rows wm*32
    const int wn   = warp & 3;             // 0..3 -> j-slice wn*32
    const int srcA = (lane & ~3) + (lq >> 1);   // shuffle source for a0/a1
    const int srcB = srcA + 2;                   // for a2/a3
    const uint32_t FULL = 0xffffffffu;

    const float scale = rsqrtf((float)CC);

    for (int phase = 0; phase < 2; phase++) {
        const int ib = (phase == 0) ? pair : 63 - pair;
        const int i0 = ib * AM;
        const int njt = (ib >> 1) + 1;     // number of 128-wide j-tiles

        // ---- load resident K tile as bf16 ----
        const float* kbp = g_k + ((size_t)b * TT + i0) * HH;
        __syncthreads();                    // prior phase fully done with smem
#pragma unroll
        for (int it = 0; it < 8; it++) {
            int fi = tid + 256 * it;        // 2048 float4 = 64 x 32
            int r  = fi >> 5;
            int c  = (fi & 31) * 4;
            float4 v = *(const float4*)(kbp + (size_t)r * HH + c);
            *(uint2*)&Kb[r * KQST + c] =
                make_uint2(bf16pair(v.x, v.y), bf16pair(v.z, v.w));
        }

        float o[2][16][4];
#pragma unroll
        for (int mt = 0; mt < 2; mt++)
#pragma unroll
            for (int nh = 0; nh < 16; nh++)
#pragma unroll
                for (int r = 0; r < 4; r++) o[mt][nh][r] = 0.f;
        float lsum[2][2] = {{0.f, 0.f}, {0.f, 0.f}};

        for (int jb = 0; jb < njt; jb++) {
            const int j0 = jb * AN;
            const float* qbp = g_q + ((size_t)b * TT + j0) * HH;
            const float* vbp = g_v + ((size_t)b * TT + j0) * HH;
            __syncthreads();                // prior iter done reading Qb/Vs
#pragma unroll
            for (int it = 0; it < 16; it++) {
                int fi = tid + 256 * it;    // 4096 float4 = 128 x 32
                int r  = fi >> 5;           // j index
                int c  = (fi & 31) * 4;     // h index
                float4 q = *(const float4*)(qbp + (size_t)r * HH + c);
                *(uint2*)&Qb[r * KQST + c] =
                    make_uint2(bf16pair(q.x, q.y), bf16pair(q.z, q.w));
                float4 v = *(const float4*)(vbp + (size_t)r * HH + c);
                *(float4*)&Vs[r * VST2 + c] =
                    make_float4(ftf32(v.x), ftf32(v.y), ftf32(v.z), ftf32(v.w));
            }
            __syncthreads();

            // ---- S = K . Q^T : warp m32 (rows wm*32) x n32 (j-slice wn*32) ----
            float sfr[2][4][4];
#pragma unroll
            for (int mt = 0; mt < 2; mt++)
#pragma unroll
                for (int nt = 0; nt < 4; nt++)
#pragma unroll
                    for (int r = 0; r < 4; r++) sfr[mt][nt][r] = 0.f;

#pragma unroll
            for (int kk = 0; kk < 8; kk++) {     // k16 steps over HH=128
                const int ke = kk * 16 + 2 * lq; // bf16 element offset
                uint32_t a[2][4], bq[4][2];
#pragma unroll
                for (int mt = 0; mt < 2; mt++) {
                    int m = wm * 32 + mt * 16 + grp;
                    a[mt][0] = *(const uint32_t*)&Kb[m * KQST + ke];
                    a[mt][1] = *(const uint32_t*)&Kb[(m + 8) * KQST + ke];
                    a[mt][2] = *(const uint32_t*)&Kb[m * KQST + ke + 8];
                    a[mt][3] = *(const uint32_t*)&Kb[(m + 8) * KQST + ke + 8];
                }
#pragma unroll
                for (int nt = 0; nt < 4; nt++) {
                    int n = wn * 32 + nt * 8 + grp;   // j row
                    bq[nt][0] = *(const uint32_t*)&Qb[n * KQST + ke];
                    bq[nt][1] = *(const uint32_t*)&Qb[n * KQST + ke + 8];
                }
#pragma unroll
                for (int mt = 0; mt < 2; mt++)
#pragma unroll
                    for (int nt = 0; nt < 4; nt++)
                        mma_bf16(sfr[mt][nt], a[mt], bq[nt]);
            }

            // ---- P = exp(scale*S), causal mask, l accumulate (registers) ----
#pragma unroll
            for (int mt = 0; mt < 2; mt++) {
                const int ig0 = i0 + wm * 32 + mt * 16 + grp;
#pragma unroll
                for (int nt = 0; nt < 4; nt++) {
                    const int jg = j0 + wn * 32 + nt * 8 + 2 * lq;
                    float p0 = (jg     <= ig0    ) ? ftf32(__expf(sfr[mt][nt][0] * scale)) : 0.f;
                    float p1 = (jg + 1 <= ig0    ) ? ftf32(__expf(sfr[mt][nt][1] * scale)) : 0.f;
                    float p2 = (jg     <= ig0 + 8) ? ftf32(__expf(sfr[mt][nt][2] * scale)) : 0.f;
                    float p3 = (jg + 1 <= ig0 + 8) ? ftf32(__expf(sfr[mt][nt][3] * scale)) : 0.f;
                    sfr[mt][nt][0] = p0; sfr[mt][nt][1] = p1;
                    sfr[mt][nt][2] = p2; sfr[mt][nt][3] = p3;
                    lsum[mt][0] += p0 + p1;
                    lsum[mt][1] += p2 + p3;
                }
            }

            // ---- O += P @ V : k=32 (warp's j-slice), n=128 (all h) ----
#pragma unroll
            for (int kk = 0; kk < 4; kk++) {       // k8 steps (= S n8 tile kk)
                float a[2][4];
#pragma unroll
                for (int mt = 0; mt < 2; mt++) {
                    float x0 = __shfl_sync(FULL, sfr[mt][kk][0], srcA);
                    float x1 = __shfl_sync(FULL, sfr[mt][kk][1], srcA);
                    float x2 = __shfl_sync(FULL, sfr[mt][kk][2], srcA);
                    float x3 = __shfl_sync(FULL, sfr[mt][kk][3], srcA);
                    float y0 = __shfl_sync(FULL, sfr[mt][kk][0], srcB);
                    float y1 = __shfl_sync(FULL, sfr[mt][kk][1], srcB);
                    float y2 = __shfl_sync(FULL, sfr[mt][kk][2], srcB);
                    float y3 = __shfl_sync(FULL, sfr[mt][kk][3], srcB);
                    a[mt][0] = (lq & 1) ? x1 : x0;   // row grp,   k lq
                    a[mt][1] = (lq & 1) ? x3 : x2;   // row grp+8, k lq
                    a[mt][2] = (lq & 1) ? y1 : y0;   // row grp,   k lq+4
                    a[mt][3] = (lq & 1) ? y3 : y2;   // row grp+8, k lq+4
                }
                const int jr = wn * 32 + kk * 8;
#pragma unroll
                for (int nh = 0; nh < 16; nh++) {
                    float bv[2];
                    int h = nh * 8 + grp;
                    bv[0] = Vs[(jr + lq) * VST2 + h];
                    bv[1] = Vs[(jr + lq + 4) * VST2 + h];
#pragma unroll
                    for (int mt = 0; mt < 2; mt++)
                        mma_tf32(o[mt][nh], a[mt], bv);
                }
            }
        }

        // ---- cross-warp reductions ----
        __syncthreads();                    // all PV reads of Vs done

        // l: quad-reduce over lq, then per-warp partial into l4[row][wn]
#pragma unroll
        for (int mt = 0; mt < 2; mt++)
#pragma unroll
            for (int h = 0; h < 2; h++) {
                lsum[mt][h] += __shfl_xor_sync(FULL, lsum[mt][h], 1);
                lsum[mt][h] += __shfl_xor_sync(FULL, lsum[mt][h], 2);
            }
        if (lq == 0) {
#pragma unroll
            for (int mt = 0; mt < 2; mt++) {
                int r = wm * 32 + mt * 16 + grp;
                l4[r * 4 + wn]       = lsum[mt][0];
                l4[(r + 8) * 4 + wn] = lsum[mt][1];
            }
        }

        // O: sequential 4-step accumulate into Ored
        for (int w = 0; w < 4; w++) {
            if (wn == w) {
#pragma unroll
                for (int mt = 0; mt < 2; mt++) {
                    int r = wm * 32 + mt * 16 + grp;
#pragma unroll
                    for (int nh = 0; nh < 16; nh++) {
                        int h = nh * 8 + 2 * lq;
                        if (w == 0) {
                            *(float2*)&Ored[r * ORST + h] =
                                make_float2(o[mt][nh][0], o[mt][nh][1]);
                            *(float2*)&Ored[(r + 8) * ORST + h] =
                                make_float2(o[mt][nh][2], o[mt][nh][3]);
                        } else {
                            float2 c0 = *(float2*)&Ored[r * ORST + h];
                            float2 c1 = *(float2*)&Ored[(r + 8) * ORST + h];
                            c0.x += o[mt][nh][0]; c0.y += o[mt][nh][1];
                            c1.x += o[mt][nh][2]; c1.y += o[mt][nh][3];
                            *(float2*)&Ored[r * ORST + h] = c0;
                            *(float2*)&Ored[(r + 8) * ORST + h] = c1;
                        }
                    }
                }
            }
            __syncthreads();
        }

        if (tid < AM)
            linv[tid] = 1.f / (l4[tid * 4] + l4[tid * 4 + 1]
                             + l4[tid * 4 + 2] + l4[tid * 4 + 3]);
        __syncthreads();

        // ---- write out ----
        float* ob = out + ((size_t)b * TT + i0) * HH;
#pragma unroll
        for (int it = 0; it < 8; it++) {
            int fi = tid + 256 * it;        // 2048 float4 = 64 x 32
            int r  = fi >> 5;
            int c  = (fi & 31) * 4;
            const float iv = linv[r];
            float4 v = *(const float4*)&Ored[r * ORST + c];
            v.x *= iv; v.y *= iv; v.z *= iv; v.w *= iv;
            *(float4*)(ob + (size_t)r * HH + c) = v;
        }
    }
}

// ---------------------------------------------------------------------------
extern "C" void kernel_launch(void* const* d_in, const int* in_sizes, int n_in,
                              void* d_out, int out_size)
{
    const float* idx = (const float*)d_in[0];
    const float* Wq  = (const float*)d_in[1];
    const float* Wk  = (const float*)d_in[2];
    const float* Wv  = (const float*)d_in[3];
    float* out = (float*)d_out;

    cudaFuncSetAttribute(attn_kernel,
                         cudaFuncAttributeMaxDynamicSharedMemorySize,
                         ATTN_SMEM_BYTES);

    qkv_kernel<<<dim3(NROW / 128, 3), 256>>>(idx, Wq, Wk, Wv);
    attn_kernel<<<dim3(32, BB), 256, ATTN_SMEM_BYTES>>>(out);
}

// round 14
// speedup vs baseline: 1.7366x; 1.1308x over previous
#include <cuda_runtime.h>
#include <cuda_bf16.h>
#include <math.h>
#include <stdint.h>

#define BB 4
#define TT 4096
#define CC 2048
#define HH 128
#define NROW (BB * TT)          // 16384

// Scratch: K,Q stored as bf16 bits; V as tf32-rounded fp32.
__device__ uint16_t g_qb[NROW * HH];
__device__ uint16_t g_kb[NROW * HH];
__device__ float    g_v[NROW * HH];

// ---------------------------------------------------------------------------
// helpers
// ---------------------------------------------------------------------------
__device__ __forceinline__ float ftf32(float x) {
    uint32_t u;
    asm("cvt.rna.tf32.f32 %0, %1;" : "=r"(u) : "f"(x));
    return __uint_as_float(u);
}

__device__ __forceinline__ uint32_t bf16pair(float lo, float hi) {
    uint32_t r;
    asm("cvt.rn.bf16x2.f32 %0, %1, %2;" : "=r"(r) : "f"(hi), "f"(lo));
    return r;
}

__device__ __forceinline__ void mma_tf32(float* d, const float* a, const float* b) {
    asm volatile(
        "mma.sync.aligned.m16n8k8.row.col.f32.tf32.tf32.f32 "
        "{%0,%1,%2,%3}, {%4,%5,%6,%7}, {%8,%9}, {%0,%1,%2,%3};"
        : "+f"(d[0]), "+f"(d[1]), "+f"(d[2]), "+f"(d[3])
        : "r"(__float_as_uint(a[0])), "r"(__float_as_uint(a[1])),
          "r"(__float_as_uint(a[2])), "r"(__float_as_uint(a[3])),
          "r"(__float_as_uint(b[0])), "r"(__float_as_uint(b[1])));
}

__device__ __forceinline__ void mma_bf16(float* d, const uint32_t* a, const uint32_t* b) {
    asm volatile(
        "mma.sync.aligned.m16n8k16.row.col.f32.bf16.bf16.f32 "
        "{%0,%1,%2,%3}, {%4,%5,%6,%7}, {%8,%9}, {%0,%1,%2,%3};"
        : "+f"(d[0]), "+f"(d[1]), "+f"(d[2]), "+f"(d[3])
        : "r"(a[0]), "r"(a[1]), "r"(a[2]), "r"(a[3]),
          "r"(b[0]), "r"(b[1]));
}

// ---------------------------------------------------------------------------
// Kernel 1a: K/Q projections in bf16 (m16n8k16).  BM=128, BN=128, BK=32.
// 256 threads = 8 warps (4x2), warp m32 x n64.  grid = (128 tiles, 2 weights).
// Output written directly as bf16 bits.
// ---------------------------------------------------------------------------
#define QBK 32
#define KQW 40      // u16 row stride: 20 words -> conflict-free fragments

__global__ __launch_bounds__(256, 2)
void qkv_kq_kernel(const float* __restrict__ idx,
                   const float* __restrict__ Wq,
                   const float* __restrict__ Wk)
{
    __shared__ uint16_t As[128][KQW];
    __shared__ uint16_t Bs[128][KQW];

    const int w = blockIdx.y;
    const float* __restrict__ Wp = (w == 0) ? Wq : Wk;
    uint16_t* __restrict__ Out = (w == 0) ? g_qb : g_kb;

    const int row0 = blockIdx.x * 128;
    const int tid  = threadIdx.x;
    const int warp = tid >> 5, lane = tid & 31;
    const int grp  = lane >> 2, lq = lane & 3;
    const int wm   = warp >> 1;
    const int wn   = warp & 1;

    int lm[4], lk[4];
#pragma unroll
    for (int i = 0; i < 4; i++) {
        int fi = tid + 256 * i;
        lm[i] = fi >> 3;
        lk[i] = (fi & 7) * 4;
    }

    float4 ra[4], rb[4];
#pragma unroll
    for (int i = 0; i < 4; i++) {
        ra[i] = *(const float4*)(idx + (size_t)(row0 + lm[i]) * CC + lk[i]);
        rb[i] = *(const float4*)(Wp + (size_t)lm[i] * CC + lk[i]);
    }
#pragma unroll
    for (int i = 0; i < 4; i++) {
        *(uint2*)&As[lm[i]][lk[i]] =
            make_uint2(bf16pair(ra[i].x, ra[i].y), bf16pair(ra[i].z, ra[i].w));
        *(uint2*)&Bs[lm[i]][lk[i]] =
            make_uint2(bf16pair(rb[i].x, rb[i].y), bf16pair(rb[i].z, rb[i].w));
    }
    __syncthreads();

    float acc[2][8][4];
#pragma unroll
    for (int mt = 0; mt < 2; mt++)
#pragma unroll
        for (int nt = 0; nt < 8; nt++)
#pragma unroll
            for (int r = 0; r < 4; r++) acc[mt][nt][r] = 0.f;

    for (int k0 = 0; k0 < CC; k0 += QBK) {
        const int kn = k0 + QBK;
        if (kn < CC) {
#pragma unroll
            for (int i = 0; i < 4; i++) {
                ra[i] = *(const float4*)(idx + (size_t)(row0 + lm[i]) * CC + kn + lk[i]);
                rb[i] = *(const float4*)(Wp + (size_t)lm[i] * CC + kn + lk[i]);
            }
        }

#pragma unroll
        for (int kk = 0; kk < 2; kk++) {
            const int ke = kk * 16 + 2 * lq;
            uint32_t a[2][4], b[8][2];
#pragma unroll
            for (int mt = 0; mt < 2; mt++) {
                int m = wm * 32 + mt * 16 + grp;
                a[mt][0] = *(const uint32_t*)&As[m][ke];
                a[mt][1] = *(const uint32_t*)&As[m + 8][ke];
                a[mt][2] = *(const uint32_t*)&As[m][ke + 8];
                a[mt][3] = *(const uint32_t*)&As[m + 8][ke + 8];
            }
#pragma unroll
            for (int nt = 0; nt < 8; nt++) {
                int n = wn * 64 + nt * 8 + grp;
                b[nt][0] = *(const uint32_t*)&Bs[n][ke];
                b[nt][1] = *(const uint32_t*)&Bs[n][ke + 8];
            }
#pragma unroll
            for (int mt = 0; mt < 2; mt++)
#pragma unroll
                for (int nt = 0; nt < 8; nt++)
                    mma_bf16(acc[mt][nt], a[mt], b[nt]);
        }
        __syncthreads();

        if (kn < CC) {
#pragma unroll
            for (int i = 0; i < 4; i++) {
                *(uint2*)&As[lm[i]][lk[i]] =
                    make_uint2(bf16pair(ra[i].x, ra[i].y), bf16pair(ra[i].z, ra[i].w));
                *(uint2*)&Bs[lm[i]][lk[i]] =
                    make_uint2(bf16pair(rb[i].x, rb[i].y), bf16pair(rb[i].z, rb[i].w));
            }
            __syncthreads();
        }
    }

#pragma unroll
    for (int mt = 0; mt < 2; mt++)
#pragma unroll
        for (int nt = 0; nt < 8; nt++) {
            int r = row0 + wm * 32 + mt * 16 + grp;
            int c = wn * 64 + nt * 8 + 2 * lq;
            *(uint32_t*)&Out[(size_t)r * HH + c] = bf16pair(acc[mt][nt][0], acc[mt][nt][1]);
            *(uint32_t*)&Out[(size_t)(r + 8) * HH + c] = bf16pair(acc[mt][nt][2], acc[mt][nt][3]);
        }
}

// ---------------------------------------------------------------------------
// Kernel 1b: V projection in tf32.  BM=64, BN=128, BK=32 -> 256 CTAs (1 wave).
// 8 warps (4x2), warp m16 x n64.  Output pre-rounded to tf32.
// ---------------------------------------------------------------------------
#define VKS 36

__global__ __launch_bounds__(256, 2)
void qkv_v_kernel(const float* __restrict__ idx,
                  const float* __restrict__ Wv)
{
    __shared__ float As[64][VKS];
    __shared__ float Bs[128][VKS];

    const int row0 = blockIdx.x * 64;
    const int tid  = threadIdx.x;
    const int warp = tid >> 5, lane = tid & 31;
    const int grp  = lane >> 2, lq = lane & 3;
    const int wm   = warp >> 1;            // 0..3 -> rows wm*16
    const int wn   = warp & 1;             // 0..1 -> cols wn*64

    int am[2], ak[2], bm[4], bk[4];
#pragma unroll
    for (int i = 0; i < 2; i++) {
        int fi = tid + 256 * i;            // 512 float4 for A
        am[i] = fi >> 3;
        ak[i] = (fi & 7) * 4;
    }
#pragma unroll
    for (int i = 0; i < 4; i++) {
        int fi = tid + 256 * i;            // 1024 float4 for B
        bm[i] = fi >> 3;
        bk[i] = (fi & 7) * 4;
    }

    float4 ra[2], rb[4];
#pragma unroll
    for (int i = 0; i < 2; i++)
        ra[i] = *(const float4*)(idx + (size_t)(row0 + am[i]) * CC + ak[i]);
#pragma unroll
    for (int i = 0; i < 4; i++)
        rb[i] = *(const float4*)(Wv + (size_t)bm[i] * CC + bk[i]);
#pragma unroll
    for (int i = 0; i < 2; i++)
        *(float4*)&As[am[i]][ak[i]] =
            make_float4(ftf32(ra[i].x), ftf32(ra[i].y), ftf32(ra[i].z), ftf32(ra[i].w));
#pragma unroll
    for (int i = 0; i < 4; i++)
        *(float4*)&Bs[bm[i]][bk[i]] =
            make_float4(ftf32(rb[i].x), ftf32(rb[i].y), ftf32(rb[i].z), ftf32(rb[i].w));
    __syncthreads();

    float acc[8][4];
#pragma unroll
    for (int nt = 0; nt < 8; nt++)
#pragma unroll
        for (int r = 0; r < 4; r++) acc[nt][r] = 0.f;

    for (int k0 = 0; k0 < CC; k0 += QBK) {
        const int kn = k0 + QBK;
        if (kn < CC) {
#pragma unroll
            for (int i = 0; i < 2; i++)
                ra[i] = *(const float4*)(idx + (size_t)(row0 + am[i]) * CC + kn + ak[i]);
#pragma unroll
            for (int i = 0; i < 4; i++)
                rb[i] = *(const float4*)(Wv + (size_t)bm[i] * CC + kn + bk[i]);
        }

#pragma unroll
        for (int kk = 0; kk < 4; kk++) {
            const int kb = kk * 8;
            float a[4], b[8][2];
            {
                int m = wm * 16 + grp;
                a[0] = As[m][kb + lq];
                a[1] = As[m + 8][kb + lq];
                a[2] = As[m][kb + lq + 4];
                a[3] = As[m + 8][kb + lq + 4];
            }
#pragma unroll
            for (int nt = 0; nt < 8; nt++) {
                int n = wn * 64 + nt * 8 + grp;
                b[nt][0] = Bs[n][kb + lq];
                b[nt][1] = Bs[n][kb + lq + 4];
            }
#pragma unroll
            for (int nt = 0; nt < 8; nt++)
                mma_tf32(acc[nt], a, b[nt]);
        }
        __syncthreads();

        if (kn < CC) {
#pragma unroll
            for (int i = 0; i < 2; i++)
                *(float4*)&As[am[i]][ak[i]] =
                    make_float4(ftf32(ra[i].x), ftf32(ra[i].y), ftf32(ra[i].z), ftf32(ra[i].w));
#pragma unroll
            for (int i = 0; i < 4; i++)
                *(float4*)&Bs[bm[i]][bk[i]] =
                    make_float4(ftf32(rb[i].x), ftf32(rb[i].y), ftf32(rb[i].z), ftf32(rb[i].w));
            __syncthreads();
        }
    }

#pragma unroll
    for (int nt = 0; nt < 8; nt++) {
        int r = row0 + wm * 16 + grp;
        int c = wn * 64 + nt * 8 + 2 * lq;
        *(float2*)&g_v[(size_t)r * HH + c] =
            make_float2(ftf32(acc[nt][0]), ftf32(acc[nt][1]));
        *(float2*)&g_v[(size_t)(r + 8) * HH + c] =
            make_float2(ftf32(acc[nt][2]), ftf32(acc[nt][3]));
    }
}

// ---------------------------------------------------------------------------
// Kernel 2: causal attention (R12 structure), K/Q read as bf16 bits, V raw.
// ---------------------------------------------------------------------------
#define AM 64
#define AN 128
#define KQST 136     // u16 row stride for Kb/Qb
#define VST2 136     // float row stride for Vs
#define ORST 132     // float row stride for Ored

#define SM_KB   0                         // u16  [64][136]  = 17408
#define SM_QB   17408                     // u16  [128][136] = 34816
#define SM_VS   52224                     // f32  [128][136] = 69632
#define SM_OR   121856                    // f32  [64][132]  = 33792
#define SM_L4   155648                    // f32  [64][4]    = 1024
#define SM_LI   156672                    // f32  [64]       = 256
#define ATTN_SMEM_BYTES 156928

__global__ __launch_bounds__(256, 1)
void attn_kernel(float* __restrict__ out)
{
    extern __shared__ char smc[];
    uint16_t* Kb = (uint16_t*)(smc + SM_KB);
    uint16_t* Qb = (uint16_t*)(smc + SM_QB);
    float* Vs   = (float*)(smc + SM_VS);
    float* Ored = (float*)(smc + SM_OR);
    float* l4   = (float*)(smc + SM_L4);
    float* linv = (float*)(smc + SM_LI);

    const int b    = blockIdx.y;
    const int pair = blockIdx.x;           // 0..31
    const int tid  = threadIdx.x;
    const int warp = tid >> 5, lane = tid & 31;
    const int grp  = lane >> 2, lq = lane & 3;
    const int wm   = warp >> 2;            // 0..1 -> rows wm*32
    const int wn   = warp & 3;             // 0..3 -> j-slice wn*32
    const int srcA = (lane & ~3) + (lq >> 1);
    const int srcB = srcA + 2;
    const uint32_t FULL = 0xffffffffu;

    const float scale = rsqrtf((float)CC);

    for (int phase = 0; phase < 2; phase++) {
        const int ib = (phase == 0) ? pair : 63 - pair;
        const int i0 = ib * AM;
        const int njt = (ib >> 1) + 1;

        // ---- load resident K tile (bf16 bits, direct copy) ----
        const uint16_t* kbp = g_kb + ((size_t)b * TT + i0) * HH;
        __syncthreads();
#pragma unroll
        for (int it = 0; it < 4; it++) {
            int fi = tid + 256 * it;        // 1024 uint4 = 64 x 16
            int r  = fi >> 4;
            int c  = (fi & 15) * 8;
            *(uint4*)&Kb[r * KQST + c] = *(const uint4*)(kbp + (size_t)r * HH + c);
        }

        float o[2][16][4];
#pragma unroll
        for (int mt = 0; mt < 2; mt++)
#pragma unroll
            for (int nh = 0; nh < 16; nh++)
#pragma unroll
                for (int r = 0; r < 4; r++) o[mt][nh][r] = 0.f;
        float lsum[2][2] = {{0.f, 0.f}, {0.f, 0.f}};

        for (int jb = 0; jb < njt; jb++) {
            const int j0 = jb * AN;
            const uint16_t* qbp = g_qb + ((size_t)b * TT + j0) * HH;
            const float* vbp = g_v + ((size_t)b * TT + j0) * HH;
            __syncthreads();
#pragma unroll
            for (int it = 0; it < 8; it++) {
                int fi = tid + 256 * it;    // 2048 uint4 = 128 x 16
                int r  = fi >> 4;
                int c  = (fi & 15) * 8;
                *(uint4*)&Qb[r * KQST + c] = *(const uint4*)(qbp + (size_t)r * HH + c);
            }
#pragma unroll
            for (int it = 0; it < 16; it++) {
                int fi = tid + 256 * it;    // 4096 float4 = 128 x 32
                int r  = fi >> 5;
                int c  = (fi & 31) * 4;
                *(float4*)&Vs[r * VST2 + c] = *(const float4*)(vbp + (size_t)r * HH + c);
            }
            __syncthreads();

            // ---- S = K . Q^T : warp m32 x n32 (j-slice) ----
            float sfr[2][4][4];
#pragma unroll
            for (int mt = 0; mt < 2; mt++)
#pragma unroll
                for (int nt = 0; nt < 4; nt++)
#pragma unroll
                    for (int r = 0; r < 4; r++) sfr[mt][nt][r] = 0.f;

#pragma unroll
            for (int kk = 0; kk < 8; kk++) {
                const int ke = kk * 16 + 2 * lq;
                uint32_t a[2][4], bq[4][2];
#pragma unroll
                for (int mt = 0; mt < 2; mt++) {
                    int m = wm * 32 + mt * 16 + grp;
                    a[mt][0] = *(const uint32_t*)&Kb[m * KQST + ke];
                    a[mt][1] = *(const uint32_t*)&Kb[(m + 8) * KQST + ke];
                    a[mt][2] = *(const uint32_t*)&Kb[m * KQST + ke + 8];
                    a[mt][3] = *(const uint32_t*)&Kb[(m + 8) * KQST + ke + 8];
                }
#pragma unroll
                for (int nt = 0; nt < 4; nt++) {
                    int n = wn * 32 + nt * 8 + grp;
                    bq[nt][0] = *(const uint32_t*)&Qb[n * KQST + ke];
                    bq[nt][1] = *(const uint32_t*)&Qb[n * KQST + ke + 8];
                }
#pragma unroll
                for (int mt = 0; mt < 2; mt++)
#pragma unroll
                    for (int nt = 0; nt < 4; nt++)
                        mma_bf16(sfr[mt][nt], a[mt], bq[nt]);
            }

            // ---- P = exp(scale*S), causal mask, l accumulate ----
#pragma unroll
            for (int mt = 0; mt < 2; mt++) {
                const int ig0 = i0 + wm * 32 + mt * 16 + grp;
#pragma unroll
                for (int nt = 0; nt < 4; nt++) {
                    const int jg = j0 + wn * 32 + nt * 8 + 2 * lq;
                    float p0 = (jg     <= ig0    ) ? ftf32(__expf(sfr[mt][nt][0] * scale)) : 0.f;
                    float p1 = (jg + 1 <= ig0    ) ? ftf32(__expf(sfr[mt][nt][1] * scale)) : 0.f;
                    float p2 = (jg     <= ig0 + 8) ? ftf32(__expf(sfr[mt][nt][2] * scale)) : 0.f;
                    float p3 = (jg + 1 <= ig0 + 8) ? ftf32(__expf(sfr[mt][nt][3] * scale)) : 0.f;
                    sfr[mt][nt][0] = p0; sfr[mt][nt][1] = p1;
                    sfr[mt][nt][2] = p2; sfr[mt][nt][3] = p3;
                    lsum[mt][0] += p0 + p1;
                    lsum[mt][1] += p2 + p3;
                }
            }

            // ---- O += P @ V ----
#pragma unroll
            for (int kk = 0; kk < 4; kk++) {
                float a[2][4];
#pragma unroll
                for (int mt = 0; mt < 2; mt++) {
                    float x0 = __shfl_sync(FULL, sfr[mt][kk][0], srcA);
                    float x1 = __shfl_sync(FULL, sfr[mt][kk][1], srcA);
                    float x2 = __shfl_sync(FULL, sfr[mt][kk][2], srcA);
                    float x3 = __shfl_sync(FULL, sfr[mt][kk][3], srcA);
                    float y0 = __shfl_sync(FULL, sfr[mt][kk][0], srcB);
                    float y1 = __shfl_sync(FULL, sfr[mt][kk][1], srcB);
                    float y2 = __shfl_sync(FULL, sfr[mt][kk][2], srcB);
                    float y3 = __shfl_sync(FULL, sfr[mt][kk][3], srcB);
                    a[mt][0] = (lq & 1) ? x1 : x0;
                    a[mt][1] = (lq & 1) ? x3 : x2;
                    a[mt][2] = (lq & 1) ? y1 : y0;
                    a[mt][3] = (lq & 1) ? y3 : y2;
                }
                const int jr = wn * 32 + kk * 8;
#pragma unroll
                for (int nh = 0; nh < 16; nh++) {
                    float bv[2];
                    int h = nh * 8 + grp;
                    bv[0] = Vs[(jr + lq) * VST2 + h];
                    bv[1] = Vs[(jr + lq + 4) * VST2 + h];
#pragma unroll
                    for (int mt = 0; mt < 2; mt++)
                        mma_tf32(o[mt][nh], a[mt], bv);
                }
            }
        }

        // ---- cross-warp reductions ----
        __syncthreads();

#pragma unroll
        for (int mt = 0; mt < 2; mt++)
#pragma unroll
            for (int h = 0; h < 2; h++) {
                lsum[mt][h] += __shfl_xor_sync(FULL, lsum[mt][h], 1);
                lsum[mt][h] += __shfl_xor_sync(FULL, lsum[mt][h], 2);
            }
        if (lq == 0) {
#pragma unroll
            for (int mt = 0; mt < 2; mt++) {
                int r = wm * 32 + mt * 16 + grp;
                l4[r * 4 + wn]       = lsum[mt][0];
                l4[(r + 8) * 4 + wn] = lsum[mt][1];
            }
        }

        for (int w = 0; w < 4; w++) {
            if (wn == w) {
#pragma unroll
                for (int mt = 0; mt < 2; mt++) {
                    int r = wm * 32 + mt * 16 + grp;
#pragma unroll
                    for (int nh = 0; nh < 16; nh++) {
                        int h = nh * 8 + 2 * lq;
                        if (w == 0) {
                            *(float2*)&Ored[r * ORST + h] =
                                make_float2(o[mt][nh][0], o[mt][nh][1]);
                            *(float2*)&Ored[(r + 8) * ORST + h] =
                                make_float2(o[mt][nh][2], o[mt][nh][3]);
                        } else {
                            float2 c0 = *(float2*)&Ored[r * ORST + h];
                            float2 c1 = *(float2*)&Ored[(r + 8) * ORST + h];
                            c0.x += o[mt][nh][0]; c0.y += o[mt][nh][1];
                            c1.x += o[mt][nh][2]; c1.y += o[mt][nh][3];
                            *(float2*)&Ored[r * ORST + h] = c0;
                            *(float2*)&Ored[(r + 8) * ORST + h] = c1;
                        }
                    }
                }
            }
            __syncthreads();
        }

        if (tid < AM)
            linv[tid] = 1.f / (l4[tid * 4] + l4[tid * 4 + 1]
                             + l4[tid * 4 + 2] + l4[tid * 4 + 3]);
        __syncthreads();

        // ---- write out ----
        float* ob = out + ((size_t)b * TT + i0) * HH;
#pragma unroll
        for (int it = 0; it < 8; it++) {
            int fi = tid + 256 * it;
            int r  = fi >> 5;
            int c  = (fi & 31) * 4;
            const float iv = linv[r];
            float4 v = *(const float4*)&Ored[r * ORST + c];
            v.x *= iv; v.y *= iv; v.z *= iv; v.w *= iv;
            *(float4*)(ob + (size_t)r * HH + c) = v;
        }
    }
}

// ---------------------------------------------------------------------------
extern "C" void kernel_launch(void* const* d_in, const int* in_sizes, int n_in,
                              void* d_out, int out_size)
{
    const float* idx = (const float*)d_in[0];
    const float* Wq  = (const float*)d_in[1];
    const float* Wk  = (const float*)d_in[2];
    const float* Wv  = (const float*)d_in[3];
    float* out = (float*)d_out;

    cudaFuncSetAttribute(attn_kernel,
                         cudaFuncAttributeMaxDynamicSharedMemorySize,
                         ATTN_SMEM_BYTES);

    qkv_kq_kernel<<<dim3(NROW / 128, 2), 256>>>(idx, Wq, Wk);
    qkv_v_kernel<<<NROW / 64, 256>>>(idx, Wv);
    attn_kernel<<<dim3(32, BB), 256, ATTN_SMEM_BYTES>>>(out);
}

// round 15
// speedup vs baseline: 1.8201x; 1.0481x over previous
#include <cuda_runtime.h>
#include <cuda_bf16.h>
#include <math.h>
#include <stdint.h>

#define BB 4
#define TT 4096
#define CC 2048
#define HH 128
#define NROW (BB * TT)          // 16384

// Scratch: K,Q stored as bf16 bits; V as tf32-rounded fp32.
__device__ uint16_t g_qb[NROW * HH];
__device__ uint16_t g_kb[NROW * HH];
__device__ float    g_v[NROW * HH];

// ---------------------------------------------------------------------------
// helpers
// ---------------------------------------------------------------------------
__device__ __forceinline__ float ftf32(float x) {
    uint32_t u;
    asm("cvt.rna.tf32.f32 %0, %1;" : "=r"(u) : "f"(x));
    return __uint_as_float(u);
}

__device__ __forceinline__ uint32_t bf16pair(float lo, float hi) {
    uint32_t r;
    asm("cvt.rn.bf16x2.f32 %0, %1, %2;" : "=r"(r) : "f"(hi), "f"(lo));
    return r;
}

__device__ __forceinline__ void mma_tf32(float* d, const float* a, const float* b) {
    asm volatile(
        "mma.sync.aligned.m16n8k8.row.col.f32.tf32.tf32.f32 "
        "{%0,%1,%2,%3}, {%4,%5,%6,%7}, {%8,%9}, {%0,%1,%2,%3};"
        : "+f"(d[0]), "+f"(d[1]), "+f"(d[2]), "+f"(d[3])
        : "r"(__float_as_uint(a[0])), "r"(__float_as_uint(a[1])),
          "r"(__float_as_uint(a[2])), "r"(__float_as_uint(a[3])),
          "r"(__float_as_uint(b[0])), "r"(__float_as_uint(b[1])));
}

__device__ __forceinline__ void mma_bf16(float* d, const uint32_t* a, const uint32_t* b) {
    asm volatile(
        "mma.sync.aligned.m16n8k16.row.col.f32.bf16.bf16.f32 "
        "{%0,%1,%2,%3}, {%4,%5,%6,%7}, {%8,%9}, {%0,%1,%2,%3};"
        : "+f"(d[0]), "+f"(d[1]), "+f"(d[2]), "+f"(d[3])
        : "r"(a[0]), "r"(a[1]), "r"(a[2]), "r"(a[3]),
          "r"(b[0]), "r"(b[1]));
}

__device__ __forceinline__ uint32_t smem_u32(const void* p) {
    uint32_t a;
    asm("{ .reg .u64 t; cvta.to.shared.u64 t, %1; cvt.u32.u64 %0, t; }"
        : "=r"(a) : "l"(p));
    return a;
}

__device__ __forceinline__ void cp16(uint32_t s, const void* g) {
    asm volatile("cp.async.cg.shared.global [%0], [%1], 16;" :: "r"(s), "l"(g));
}
#define CP_COMMIT() asm volatile("cp.async.commit_group;" ::: "memory")
#define CP_WAIT(n)  asm volatile("cp.async.wait_group %0;" :: "n"(n) : "memory")

// ---------------------------------------------------------------------------
// Kernel 1a: K/Q projections in bf16 (m16n8k16).  BM=128, BN=128, BK=32.
// ---------------------------------------------------------------------------
#define QBK 32
#define KQW 40      // u16 row stride

__global__ __launch_bounds__(256, 2)
void qkv_kq_kernel(const float* __restrict__ idx,
                   const float* __restrict__ Wq,
                   const float* __restrict__ Wk)
{
    __shared__ uint16_t As[128][KQW];
    __shared__ uint16_t Bs[128][KQW];

    const int w = blockIdx.y;
    const float* __restrict__ Wp = (w == 0) ? Wq : Wk;
    uint16_t* __restrict__ Out = (w == 0) ? g_qb : g_kb;

    const int row0 = blockIdx.x * 128;
    const int tid  = threadIdx.x;
    const int warp = tid >> 5, lane = tid & 31;
    const int grp  = lane >> 2, lq = lane & 3;
    const int wm   = warp >> 1;
    const int wn   = warp & 1;

    int lm[4], lk[4];
#pragma unroll
    for (int i = 0; i < 4; i++) {
        int fi = tid + 256 * i;
        lm[i] = fi >> 3;
        lk[i] = (fi & 7) * 4;
    }

    float4 ra[4], rb[4];
#pragma unroll
    for (int i = 0; i < 4; i++) {
        ra[i] = *(const float4*)(idx + (size_t)(row0 + lm[i]) * CC + lk[i]);
        rb[i] = *(const float4*)(Wp + (size_t)lm[i] * CC + lk[i]);
    }
#pragma unroll
    for (int i = 0; i < 4; i++) {
        *(uint2*)&As[lm[i]][lk[i]] =
            make_uint2(bf16pair(ra[i].x, ra[i].y), bf16pair(ra[i].z, ra[i].w));
        *(uint2*)&Bs[lm[i]][lk[i]] =
            make_uint2(bf16pair(rb[i].x, rb[i].y), bf16pair(rb[i].z, rb[i].w));
    }
    __syncthreads();

    float acc[2][8][4];
#pragma unroll
    for (int mt = 0; mt < 2; mt++)
#pragma unroll
        for (int nt = 0; nt < 8; nt++)
#pragma unroll
            for (int r = 0; r < 4; r++) acc[mt][nt][r] = 0.f;

    for (int k0 = 0; k0 < CC; k0 += QBK) {
        const int kn = k0 + QBK;
        if (kn < CC) {
#pragma unroll
            for (int i = 0; i < 4; i++) {
                ra[i] = *(const float4*)(idx + (size_t)(row0 + lm[i]) * CC + kn + lk[i]);
                rb[i] = *(const float4*)(Wp + (size_t)lm[i] * CC + kn + lk[i]);
            }
        }

#pragma unroll
        for (int kk = 0; kk < 2; kk++) {
            const int ke = kk * 16 + 2 * lq;
            uint32_t a[2][4], b[8][2];
#pragma unroll
            for (int mt = 0; mt < 2; mt++) {
                int m = wm * 32 + mt * 16 + grp;
                a[mt][0] = *(const uint32_t*)&As[m][ke];
                a[mt][1] = *(const uint32_t*)&As[m + 8][ke];
                a[mt][2] = *(const uint32_t*)&As[m][ke + 8];
                a[mt][3] = *(const uint32_t*)&As[m + 8][ke + 8];
            }
#pragma unroll
            for (int nt = 0; nt < 8; nt++) {
                int n = wn * 64 + nt * 8 + grp;
                b[nt][0] = *(const uint32_t*)&Bs[n][ke];
                b[nt][1] = *(const uint32_t*)&Bs[n][ke + 8];
            }
#pragma unroll
            for (int mt = 0; mt < 2; mt++)
#pragma unroll
                for (int nt = 0; nt < 8; nt++)
                    mma_bf16(acc[mt][nt], a[mt], b[nt]);
        }
        __syncthreads();

        if (kn < CC) {
#pragma unroll
            for (int i = 0; i < 4; i++) {
                *(uint2*)&As[lm[i]][lk[i]] =
                    make_uint2(bf16pair(ra[i].x, ra[i].y), bf16pair(ra[i].z, ra[i].w));
                *(uint2*)&Bs[lm[i]][lk[i]] =
                    make_uint2(bf16pair(rb[i].x, rb[i].y), bf16pair(rb[i].z, rb[i].w));
            }
            __syncthreads();
        }
    }

#pragma unroll
    for (int mt = 0; mt < 2; mt++)
#pragma unroll
        for (int nt = 0; nt < 8; nt++) {
            int r = row0 + wm * 32 + mt * 16 + grp;
            int c = wn * 64 + nt * 8 + 2 * lq;
            *(uint32_t*)&Out[(size_t)r * HH + c] = bf16pair(acc[mt][nt][0], acc[mt][nt][1]);
            *(uint32_t*)&Out[(size_t)(r + 8) * HH + c] = bf16pair(acc[mt][nt][2], acc[mt][nt][3]);
        }
}

// ---------------------------------------------------------------------------
// Kernel 1b: V projection in tf32.  BM=64 -> 256 CTAs (one wave).
// ---------------------------------------------------------------------------
#define VKS 36

__global__ __launch_bounds__(256, 2)
void qkv_v_kernel(const float* __restrict__ idx,
                  const float* __restrict__ Wv)
{
    __shared__ float As[64][VKS];
    __shared__ float Bs[128][VKS];

    const int row0 = blockIdx.x * 64;
    const int tid  = threadIdx.x;
    const int warp = tid >> 5, lane = tid & 31;
    const int grp  = lane >> 2, lq = lane & 3;
    const int wm   = warp >> 1;
    const int wn   = warp & 1;

    int am[2], ak[2], bm[4], bk[4];
#pragma unroll
    for (int i = 0; i < 2; i++) {
        int fi = tid + 256 * i;
        am[i] = fi >> 3;
        ak[i] = (fi & 7) * 4;
    }
#pragma unroll
    for (int i = 0; i < 4; i++) {
        int fi = tid + 256 * i;
        bm[i] = fi >> 3;
        bk[i] = (fi & 7) * 4;
    }

    float4 ra[2], rb[4];
#pragma unroll
    for (int i = 0; i < 2; i++)
        ra[i] = *(const float4*)(idx + (size_t)(row0 + am[i]) * CC + ak[i]);
#pragma unroll
    for (int i = 0; i < 4; i++)
        rb[i] = *(const float4*)(Wv + (size_t)bm[i] * CC + bk[i]);
#pragma unroll
    for (int i = 0; i < 2; i++)
        *(float4*)&As[am[i]][ak[i]] =
            make_float4(ftf32(ra[i].x), ftf32(ra[i].y), ftf32(ra[i].z), ftf32(ra[i].w));
#pragma unroll
    for (int i = 0; i < 4; i++)
        *(float4*)&Bs[bm[i]][bk[i]] =
            make_float4(ftf32(rb[i].x), ftf32(rb[i].y), ftf32(rb[i].z), ftf32(rb[i].w));
    __syncthreads();

    float acc[8][4];
#pragma unroll
    for (int nt = 0; nt < 8; nt++)
#pragma unroll
        for (int r = 0; r < 4; r++) acc[nt][r] = 0.f;

    for (int k0 = 0; k0 < CC; k0 += QBK) {
        const int kn = k0 + QBK;
        if (kn < CC) {
#pragma unroll
            for (int i = 0; i < 2; i++)
                ra[i] = *(const float4*)(idx + (size_t)(row0 + am[i]) * CC + kn + ak[i]);
#pragma unroll
            for (int i = 0; i < 4; i++)
                rb[i] = *(const float4*)(Wv + (size_t)bm[i] * CC + kn + bk[i]);
        }

#pragma unroll
        for (int kk = 0; kk < 4; kk++) {
            const int kb = kk * 8;
            float a[4], b[8][2];
            {
                int m = wm * 16 + grp;
                a[0] = As[m][kb + lq];
                a[1] = As[m + 8][kb + lq];
                a[2] = As[m][kb + lq + 4];
                a[3] = As[m + 8][kb + lq + 4];
            }
#pragma unroll
            for (int nt = 0; nt < 8; nt++) {
                int n = wn * 64 + nt * 8 + grp;
                b[nt][0] = Bs[n][kb + lq];
                b[nt][1] = Bs[n][kb + lq + 4];
            }
#pragma unroll
            for (int nt = 0; nt < 8; nt++)
                mma_tf32(acc[nt], a, b[nt]);
        }
        __syncthreads();

        if (kn < CC) {
#pragma unroll
            for (int i = 0; i < 2; i++)
                *(float4*)&As[am[i]][ak[i]] =
                    make_float4(ftf32(ra[i].x), ftf32(ra[i].y), ftf32(ra[i].z), ftf32(ra[i].w));
#pragma unroll
            for (int i = 0; i < 4; i++)
                *(float4*)&Bs[bm[i]][bk[i]] =
                    make_float4(ftf32(rb[i].x), ftf32(rb[i].y), ftf32(rb[i].z), ftf32(rb[i].w));
            __syncthreads();
        }
    }

#pragma unroll
    for (int nt = 0; nt < 8; nt++) {
        int r = row0 + wm * 16 + grp;
        int c = wn * 64 + nt * 8 + 2 * lq;
        *(float2*)&g_v[(size_t)r * HH + c] =
            make_float2(ftf32(acc[nt][0]), ftf32(acc[nt][1]));
        *(float2*)&g_v[(size_t)(r + 8) * HH + c] =
            make_float2(ftf32(acc[nt][2]), ftf32(acc[nt][3]));
    }
}

// ---------------------------------------------------------------------------
// Kernel 2: causal attention, cp.async 2-group pipeline, double-buffered Q.
// Per j-tile: commit V -> wait(Q) -> S mma -> commit Q(next) -> exp -> wait(V)
// -> PV.  Invariant: 2 commits + 2 wait_group(1) per iteration.
// ---------------------------------------------------------------------------
#define AM 64
#define AN 128
#define KQST 136     // u16 row stride for Kb/Qb
#define VST2 136     // float row stride for Vs
#define ORST 132     // float row stride for Ored

#define SM_KB   0                         // u16  [64][136]   = 17408
#define SM_QB0  17408                     // u16  [128][136]  = 34816
#define SM_QB1  52224                     // u16  [128][136]  = 34816
#define SM_VS   87040                     // f32  [128][136]  = 69632
#define SM_OR   156672                    // f32  [64][132]   = 33792
#define SM_L4   190464                    // f32  [64][4]     = 1024
#define SM_LI   191488                    // f32  [64]        = 256
#define ATTN_SMEM_BYTES 191744

__global__ __launch_bounds__(256, 1)
void attn_kernel(float* __restrict__ out)
{
    extern __shared__ char smc[];
    uint16_t* Kb = (uint16_t*)(smc + SM_KB);
    float* Vs   = (float*)(smc + SM_VS);
    float* Ored = (float*)(smc + SM_OR);
    float* l4   = (float*)(smc + SM_L4);
    float* linv = (float*)(smc + SM_LI);
    const uint32_t sb = smem_u32(smc);

    const int b    = blockIdx.y;
    const int pair = blockIdx.x;           // 0..31
    const int tid  = threadIdx.x;
    const int warp = tid >> 5, lane = tid & 31;
    const int grp  = lane >> 2, lq = lane & 3;
    const int wm   = warp >> 2;
    const int wn   = warp & 3;
    const int srcA = (lane & ~3) + (lq >> 1);
    const int srcB = srcA + 2;
    const uint32_t FULL = 0xffffffffu;

    const float scale = rsqrtf((float)CC);

    // per-thread cp.async coords
    int qr[8], qc[8];                      // Q/K tiles: uint4 over u16
#pragma unroll
    for (int it = 0; it < 8; it++) {
        int fi = tid + 256 * it;           // 2048 uint4 = 128 x 16
        qr[it] = fi >> 4;
        qc[it] = (fi & 15) * 8;
    }
    int vr[16], vc[16];                    // V tile: float4
#pragma unroll
    for (int it = 0; it < 16; it++) {
        int fi = tid + 256 * it;           // 4096 float4 = 128 x 32
        vr[it] = fi >> 5;
        vc[it] = (fi & 31) * 4;
    }

    for (int phase = 0; phase < 2; phase++) {
        const int ib = (phase == 0) ? pair : 63 - pair;
        const int i0 = ib * AM;
        const int njt = (ib >> 1) + 1;

        __syncthreads();                    // prior phase fully done with smem

        // ---- load resident K tile (plain copy) ----
        const uint16_t* kbp = g_kb + ((size_t)b * TT + i0) * HH;
#pragma unroll
        for (int it = 0; it < 4; it++) {
            int fi = tid + 256 * it;        // 1024 uint4 = 64 x 16
            int r  = fi >> 4;
            int c  = (fi & 15) * 8;
            *(uint4*)&Kb[r * KQST + c] = *(const uint4*)(kbp + (size_t)r * HH + c);
        }

        // ---- prefetch Q tile 0 into buffer 0 ----
        {
            const uint16_t* qbp = g_qb + ((size_t)b * TT) * HH;
#pragma unroll
            for (int it = 0; it < 8; it++)
                cp16(sb + SM_QB0 + (qr[it] * KQST + qc[it]) * 2,
                     qbp + (size_t)qr[it] * HH + qc[it]);
            CP_COMMIT();
        }

        float o[2][16][4];
#pragma unroll
        for (int mt = 0; mt < 2; mt++)
#pragma unroll
            for (int nh = 0; nh < 16; nh++)
#pragma unroll
                for (int r = 0; r < 4; r++) o[mt][nh][r] = 0.f;
        float lsum[2][2] = {{0.f, 0.f}, {0.f, 0.f}};

        for (int jb = 0; jb < njt; jb++) {
            const int j0 = jb * AN;
            const uint32_t qbuf = (jb & 1) ? SM_QB1 : SM_QB0;
            uint16_t* Qb = (uint16_t*)(smc + qbuf);

            __syncthreads();                // prev PV done with Vs; K stores visible

            // ---- issue V(jb) ----
            {
                const float* vbp = g_v + ((size_t)b * TT + j0) * HH;
#pragma unroll
                for (int it = 0; it < 16; it++)
                    cp16(sb + SM_VS + (vr[it] * VST2 + vc[it]) * 4,
                         vbp + (size_t)vr[it] * HH + vc[it]);
                CP_COMMIT();
            }

            CP_WAIT(1);                     // Q(jb) complete (V(jb) may pend)
            __syncthreads();

            // ---- S = K . Q^T : warp m32 x n32 (j-slice) ----
            float sfr[2][4][4];
#pragma unroll
            for (int mt = 0; mt < 2; mt++)
#pragma unroll
                for (int nt = 0; nt < 4; nt++)
#pragma unroll
                    for (int r = 0; r < 4; r++) sfr[mt][nt][r] = 0.f;

#pragma unroll
            for (int kk = 0; kk < 8; kk++) {
                const int ke = kk * 16 + 2 * lq;
                uint32_t a[2][4], bq[4][2];
#pragma unroll
                for (int mt = 0; mt < 2; mt++) {
                    int m = wm * 32 + mt * 16 + grp;
                    a[mt][0] = *(const uint32_t*)&Kb[m * KQST + ke];
                    a[mt][1] = *(const uint32_t*)&Kb[(m + 8) * KQST + ke];
                    a[mt][2] = *(const uint32_t*)&Kb[m * KQST + ke + 8];
                    a[mt][3] = *(const uint32_t*)&Kb[(m + 8) * KQST + ke + 8];
                }
#pragma unroll
                for (int nt = 0; nt < 4; nt++) {
                    int n = wn * 32 + nt * 8 + grp;
                    bq[nt][0] = *(const uint32_t*)&Qb[n * KQST + ke];
                    bq[nt][1] = *(const uint32_t*)&Qb[n * KQST + ke + 8];
                }
#pragma unroll
                for (int mt = 0; mt < 2; mt++)
#pragma unroll
                    for (int nt = 0; nt < 4; nt++)
                        mma_bf16(sfr[mt][nt], a[mt], bq[nt]);
            }

            // ---- issue Q(jb+1) into other buffer ----
            if (jb + 1 < njt) {
                const uint32_t qn = (jb & 1) ? SM_QB0 : SM_QB1;
                const uint16_t* qbp = g_qb + ((size_t)b * TT + (size_t)(jb + 1) * AN) * HH;
#pragma unroll
                for (int it = 0; it < 8; it++)
                    cp16(sb + qn + (qr[it] * KQST + qc[it]) * 2,
                         qbp + (size_t)qr[it] * HH + qc[it]);
            }
            CP_COMMIT();                    // always commit (may be empty)

            // ---- P = exp(scale*S), causal mask, l accumulate ----
#pragma unroll
            for (int mt = 0; mt < 2; mt++) {
                const int ig0 = i0 + wm * 32 + mt * 16 + grp;
#pragma unroll
                for (int nt = 0; nt < 4; nt++) {
                    const int jg = j0 + wn * 32 + nt * 8 + 2 * lq;
                    float p0 = (jg     <= ig0    ) ? ftf32(__expf(sfr[mt][nt][0] * scale)) : 0.f;
                    float p1 = (jg + 1 <= ig0    ) ? ftf32(__expf(sfr[mt][nt][1] * scale)) : 0.f;
                    float p2 = (jg     <= ig0 + 8) ? ftf32(__expf(sfr[mt][nt][2] * scale)) : 0.f;
                    float p3 = (jg + 1 <= ig0 + 8) ? ftf32(__expf(sfr[mt][nt][3] * scale)) : 0.f;
                    sfr[mt][nt][0] = p0; sfr[mt][nt][1] = p1;
                    sfr[mt][nt][2] = p2; sfr[mt][nt][3] = p3;
                    lsum[mt][0] += p0 + p1;
                    lsum[mt][1] += p2 + p3;
                }
            }

            CP_WAIT(1);                     // V(jb) complete (Q(jb+1) may pend)
            __syncthreads();

            // ---- O += P @ V ----
#pragma unroll
            for (int kk = 0; kk < 4; kk++) {
                float a[2][4];
#pragma unroll
                for (int mt = 0; mt < 2; mt++) {
                    float x0 = __shfl_sync(FULL, sfr[mt][kk][0], srcA);
                    float x1 = __shfl_sync(FULL, sfr[mt][kk][1], srcA);
                    float x2 = __shfl_sync(FULL, sfr[mt][kk][2], srcA);
                    float x3 = __shfl_sync(FULL, sfr[mt][kk][3], srcA);
                    float y0 = __shfl_sync(FULL, sfr[mt][kk][0], srcB);
                    float y1 = __shfl_sync(FULL, sfr[mt][kk][1], srcB);
                    float y2 = __shfl_sync(FULL, sfr[mt][kk][2], srcB);
                    float y3 = __shfl_sync(FULL, sfr[mt][kk][3], srcB);
                    a[mt][0] = (lq & 1) ? x1 : x0;
                    a[mt][1] = (lq & 1) ? x3 : x2;
                    a[mt][2] = (lq & 1) ? y1 : y0;
                    a[mt][3] = (lq & 1) ? y3 : y2;
                }
                const int jr = wn * 32 + kk * 8;
#pragma unroll
                for (int nh = 0; nh < 16; nh++) {
                    float bv[2];
                    int h = nh * 8 + grp;
                    bv[0] = Vs[(jr + lq) * VST2 + h];
                    bv[1] = Vs[(jr + lq + 4) * VST2 + h];
#pragma unroll
                    for (int mt = 0; mt < 2; mt++)
                        mma_tf32(o[mt][nh], a[mt], bv);
                }
            }
        }

        // ---- drain pipeline, then cross-warp reductions ----
        CP_WAIT(0);
        __syncthreads();

#pragma unroll
        for (int mt = 0; mt < 2; mt++)
#pragma unroll
            for (int h = 0; h < 2; h++) {
                lsum[mt][h] += __shfl_xor_sync(FULL, lsum[mt][h], 1);
                lsum[mt][h] += __shfl_xor_sync(FULL, lsum[mt][h], 2);
            }
        if (lq == 0) {
#pragma unroll
            for (int mt = 0; mt < 2; mt++) {
                int r = wm * 32 + mt * 16 + grp;
                l4[r * 4 + wn]       = lsum[mt][0];
                l4[(r + 8) * 4 + wn] = lsum[mt][1];
            }
        }

        for (int w = 0; w < 4; w++) {
            if (wn == w) {
#pragma unroll
                for (int mt = 0; mt < 2; mt++) {
                    int r = wm * 32 + mt * 16 + grp;
#pragma unroll
                    for (int nh = 0; nh < 16; nh++) {
                        int h = nh * 8 + 2 * lq;
                        if (w == 0) {
                            *(float2*)&Ored[r * ORST + h] =
                                make_float2(o[mt][nh][0], o[mt][nh][1]);
                            *(float2*)&Ored[(r + 8) * ORST + h] =
                                make_float2(o[mt][nh][2], o[mt][nh][3]);
                        } else {
                            float2 c0 = *(float2*)&Ored[r * ORST + h];
                            float2 c1 = *(float2*)&Ored[(r + 8) * ORST + h];
                            c0.x += o[mt][nh][0]; c0.y += o[mt][nh][1];
                            c1.x += o[mt][nh][2]; c1.y += o[mt][nh][3];
                            *(float2*)&Ored[r * ORST + h] = c0;
                            *(float2*)&Ored[(r + 8) * ORST + h] = c1;
                        }
                    }
                }
            }
            __syncthreads();
        }

        if (tid < AM)
            linv[tid] = 1.f / (l4[tid * 4] + l4[tid * 4 + 1]
                             + l4[tid * 4 + 2] + l4[tid * 4 + 3]);
        __syncthreads();

        // ---- write out ----
        float* ob = out + ((size_t)b * TT + i0) * HH;
#pragma unroll
        for (int it = 0; it < 8; it++) {
            int fi = tid + 256 * it;
            int r  = fi >> 5;
            int c  = (fi & 31) * 4;
            const float iv = linv[r];
            float4 v = *(const float4*)&Ored[r * ORST + c];
            v.x *= iv; v.y *= iv; v.z *= iv; v.w *= iv;
            *(float4*)(ob + (size_t)r * HH + c) = v;
        }
    }
}

// ---------------------------------------------------------------------------
extern "C" void kernel_launch(void* const* d_in, const int* in_sizes, int n_in,
                              void* d_out, int out_size)
{
    const float* idx = (const float*)d_in[0];
    const float* Wq  = (const float*)d_in[1];
    const float* Wk  = (const float*)d_in[2];
    const float* Wv  = (const float*)d_in[3];
    float* out = (float*)d_out;

    cudaFuncSetAttribute(attn_kernel,
                         cudaFuncAttributeMaxDynamicSharedMemorySize,
                         ATTN_SMEM_BYTES);

    qkv_kq_kernel<<<dim3(NROW / 128, 2), 256>>>(idx, Wq, Wk);
    qkv_v_kernel<<<NROW / 64, 256>>>(idx, Wv);
    attn_kernel<<<dim3(32, BB), 256, ATTN_SMEM_BYTES>>>(out);
}